// round 2
// baseline (speedup 1.0000x reference)
#include <cuda_runtime.h>

// ---- problem constants (hardcoded in reference module) ----
#define NN 57254
#define EE 916064
#define NPAD 57344           // 1024*56, padded counter array
#define BT 32768             // B*T

// ---- device scratch (static: no allocation allowed) ----
__device__ float g_h0[NN * 128];
__device__ float g_h1[NN * 128];
__device__ float g_z [NN * 128];
__device__ float g_el[NN * 8];
__device__ float g_er[NN * 8];
__device__ int   g_rowptr[NN + 1];
__device__ int   g_cnt[NPAD];
__device__ int   g_csrc[EE];

// ---------------------------------------------------------------------------
// CSR build: count (int4), single-block 2-pass scan, scatter
// ---------------------------------------------------------------------------
__global__ void k_count(const int4* __restrict__ dst4) {
    int i = blockIdx.x * blockDim.x + threadIdx.x;
    if (i < EE / 4) {
        int4 d = dst4[i];
        atomicAdd(&g_cnt[d.x], 1);
        atomicAdd(&g_cnt[d.y], 1);
        atomicAdd(&g_cnt[d.z], 1);
        atomicAdd(&g_cnt[d.w], 1);
    }
}

__global__ __launch_bounds__(1024) void k_scan() {
    __shared__ int wsum[32];
    int t = threadIdx.x;
    int lane = t & 31, wid = t >> 5;
    const int4* c4 = (const int4*)g_cnt;

    // pass 1: per-thread total over 56 counters (14 int4)
    int tot = 0;
    #pragma unroll
    for (int j = 0; j < 14; j++) {
        int4 v = c4[t * 14 + j];
        tot += v.x + v.y + v.z + v.w;
    }
    // warp inclusive scan
    int s = tot;
    #pragma unroll
    for (int o = 1; o < 32; o <<= 1) {
        int u = __shfl_up_sync(0xffffffffu, s, o);
        if (lane >= o) s += u;
    }
    if (lane == 31) wsum[wid] = s;
    __syncthreads();
    if (wid == 0) {
        int wv = wsum[lane];
        #pragma unroll
        for (int o = 1; o < 32; o <<= 1) {
            int u = __shfl_up_sync(0xffffffffu, wv, o);
            if (lane >= o) wv += u;
        }
        wsum[lane] = wv;
    }
    __syncthreads();
    int run = s - tot + (wid > 0 ? wsum[wid - 1] : 0);   // exclusive prefix

    // pass 2: re-read counters, emit exclusive prefix
    #pragma unroll
    for (int j = 0; j < 14; j++) {
        int4 v = c4[t * 14 + j];
        int idx = t * 56 + j * 4;
        if (idx + 3 < NN) {
            int4 o;
            o.x = run;           o.y = run + v.x;
            o.z = run + v.x + v.y; o.w = run + v.x + v.y + v.z;
            *(int4*)(g_rowptr + idx) = o;
            run += v.x + v.y + v.z + v.w;
        } else {
            if (idx     < NN) g_rowptr[idx]     = run; run += v.x;
            if (idx + 1 < NN) g_rowptr[idx + 1] = run; run += v.y;
            if (idx + 2 < NN) g_rowptr[idx + 2] = run; run += v.z;
            if (idx + 3 < NN) g_rowptr[idx + 3] = run; run += v.w;
        }
    }
    if (t == 1023) g_rowptr[NN] = EE;
}

__global__ void k_scatter(const int* __restrict__ src, const int* __restrict__ dst) {
    int i = blockIdx.x * blockDim.x + threadIdx.x;
    if (i >= EE) return;
    int d = dst[i];
    int pos = g_rowptr[d] + atomicAdd(&g_cnt[d], 1);
    g_csrc[pos] = src[i];
}

// ---------------------------------------------------------------------------
// z = h @ W  (NNx128 @ 128x128 fp32).
// 64x128 tile, 128 threads, 8x8 register tile/thread, XOR-swizzled sH.
// Optional fused gather (nf != null -> rows come from emb[nf[r]], also writes hout).
// ---------------------------------------------------------------------------
__global__ __launch_bounds__(128) void k_gemm(const float* __restrict__ hsrc,
                                              const int* __restrict__ nf,
                                              const float* __restrict__ W,
                                              float* __restrict__ z,
                                              float* __restrict__ hout) {
    __shared__ float sW[32 * 128];
    __shared__ float sH[64 * 36];
    __shared__ int srow[64];
    int t = threadIdx.x;
    int rowbase = blockIdx.x * 64;
    if (t < 64) {
        int r = rowbase + t;
        srow[t] = (r < NN) ? (nf ? nf[r] : r) : -1;
    }
    __syncthreads();

    int tc = t & 15;          // cols 8*tc .. 8*tc+7
    int tr = t >> 4;          // rows tr*8 .. tr*8+7
    int hswz = (tr & 1) << 2;
    float acc[8][8] = {};

    for (int kb = 0; kb < 128; kb += 32) {
        #pragma unroll
        for (int r8 = 0; r8 < 8; r8++) {
            int idx = t + r8 * 128;
            ((float4*)sW)[idx] = ((const float4*)(W + kb * 128))[idx];
        }
        #pragma unroll
        for (int r4 = 0; r4 < 4; r4++) {
            int li = t + r4 * 128;     // 0..511
            int row = li >> 3, kq = li & 7;
            int sidx = srow[row];
            float4 v = make_float4(0.f, 0.f, 0.f, 0.f);
            if (sidx >= 0) v = *(const float4*)(hsrc + (long)sidx * 128 + kb + kq * 4);
            int col = (kq * 4) ^ ((row & 8) ? 4 : 0);
            *(float4*)(sH + row * 36 + col) = v;
            if (hout != nullptr && sidx >= 0)
                *(float4*)(hout + (long)(rowbase + row) * 128 + kb + kq * 4) = v;
        }
        __syncthreads();

        #pragma unroll
        for (int kk = 0; kk < 32; kk++) {
            float4 w0 = *(float4*)(sW + kk * 128 + tc * 8);
            float4 w1 = *(float4*)(sW + kk * 128 + tc * 8 + 4);
            float wv[8] = {w0.x, w0.y, w0.z, w0.w, w1.x, w1.y, w1.z, w1.w};
            #pragma unroll
            for (int i = 0; i < 8; i++) {
                float hv = sH[(tr * 8 + i) * 36 + (kk ^ hswz)];
                #pragma unroll
                for (int j = 0; j < 8; j++) acc[i][j] += hv * wv[j];
            }
        }
        __syncthreads();
    }
    #pragma unroll
    for (int i = 0; i < 8; i++) {
        int row = rowbase + tr * 8 + i;
        if (row < NN) {
            *(float4*)(z + (long)row * 128 + tc * 8) =
                make_float4(acc[i][0], acc[i][1], acc[i][2], acc[i][3]);
            *(float4*)(z + (long)row * 128 + tc * 8 + 4) =
                make_float4(acc[i][4], acc[i][5], acc[i][6], acc[i][7]);
        }
    }
}

// ---------------------------------------------------------------------------
// el[n,h] = sum_o z[n,h,o]*al[h,o];  er likewise
// ---------------------------------------------------------------------------
__global__ void k_scores(const float* __restrict__ z,
                         const float* __restrict__ al,
                         const float* __restrict__ ar,
                         float* __restrict__ el,
                         float* __restrict__ er) {
    int i = blockIdx.x * blockDim.x + threadIdx.x;
    if (i >= NN * 8) return;
    int n = i >> 3, hd = i & 7;
    const float4* zp  = (const float4*)(z + (long)n * 128 + hd * 16);
    const float4* alp = (const float4*)(al + hd * 16);
    const float4* arp = (const float4*)(ar + hd * 16);
    float sl = 0.f, sr = 0.f;
    #pragma unroll
    for (int j = 0; j < 4; j++) {
        float4 zz = zp[j], a = alp[j], r = arp[j];
        sl += zz.x * a.x + zz.y * a.y + zz.z * a.z + zz.w * a.w;
        sr += zz.x * r.x + zz.y * r.y + zz.z * r.z + zz.w * r.w;
    }
    el[i] = sl;
    er[i] = sr;
}

// ---------------------------------------------------------------------------
// Per-dst edge softmax + aggregate + residual + bias (+ leaky_relu).
// One warp/node, 4-edge software pipeline for MLP.
// ---------------------------------------------------------------------------
__global__ __launch_bounds__(256) void k_aggregate(const float* __restrict__ z,
                                                   const float* __restrict__ el,
                                                   const float* __restrict__ er,
                                                   const float* __restrict__ hin,
                                                   const float* __restrict__ bias,
                                                   float* __restrict__ hout,
                                                   int activate) {
    int warp = (blockIdx.x * blockDim.x + threadIdx.x) >> 5;
    int lane = threadIdx.x & 31;
    if (warp >= NN) return;
    int hd = lane >> 2;
    float erh = er[warp * 8 + hd];
    int beg = g_rowptr[warp], end = g_rowptr[warp + 1];
    const float4* z4 = (const float4*)z;
    float s = 0.f;
    float4 acc = make_float4(0.f, 0.f, 0.f, 0.f);

    int e = beg;
    for (; e + 4 <= end; e += 4) {
        int s0 = g_csrc[e],     s1 = g_csrc[e + 1];
        int s2 = g_csrc[e + 2], s3 = g_csrc[e + 3];
        float x0 = el[s0 * 8 + hd], x1 = el[s1 * 8 + hd];
        float x2 = el[s2 * 8 + hd], x3 = el[s3 * 8 + hd];
        float4 za = z4[s0 * 32 + lane], zb = z4[s1 * 32 + lane];
        float4 zc = z4[s2 * 32 + lane], zd = z4[s3 * 32 + lane];
        x0 += erh; x0 = x0 > 0.f ? x0 : 0.2f * x0; float a0 = __expf(x0);
        x1 += erh; x1 = x1 > 0.f ? x1 : 0.2f * x1; float a1 = __expf(x1);
        x2 += erh; x2 = x2 > 0.f ? x2 : 0.2f * x2; float a2 = __expf(x2);
        x3 += erh; x3 = x3 > 0.f ? x3 : 0.2f * x3; float a3 = __expf(x3);
        s += a0; acc.x += a0 * za.x; acc.y += a0 * za.y; acc.z += a0 * za.z; acc.w += a0 * za.w;
        s += a1; acc.x += a1 * zb.x; acc.y += a1 * zb.y; acc.z += a1 * zb.z; acc.w += a1 * zb.w;
        s += a2; acc.x += a2 * zc.x; acc.y += a2 * zc.y; acc.z += a2 * zc.z; acc.w += a2 * zc.w;
        s += a3; acc.x += a3 * zd.x; acc.y += a3 * zd.y; acc.z += a3 * zd.z; acc.w += a3 * zd.w;
    }
    for (; e < end; e++) {
        int sr = g_csrc[e];
        float x = el[sr * 8 + hd] + erh;
        x = x > 0.f ? x : 0.2f * x;
        float a = __expf(x);
        s += a;
        float4 zz = z4[sr * 32 + lane];
        acc.x += a * zz.x; acc.y += a * zz.y;
        acc.z += a * zz.z; acc.w += a * zz.w;
    }
    float inv = (s > 0.f) ? (1.f / s) : 0.f;
    float4 hv = ((const float4*)hin)[warp * 32 + lane];
    float4 bv = ((const float4*)bias)[lane];
    float4 o;
    o.x = acc.x * inv + hv.x + bv.x;
    o.y = acc.y * inv + hv.y + bv.y;
    o.z = acc.z * inv + hv.z + bv.z;
    o.w = acc.w * inv + hv.w + bv.w;
    if (activate) {
        o.x = o.x > 0.f ? o.x : 0.01f * o.x;
        o.y = o.y > 0.f ? o.y : 0.01f * o.y;
        o.z = o.z > 0.f ? o.z : 0.01f * o.z;
        o.w = o.w > 0.f ? o.w : 0.01f * o.w;
    }
    ((float4*)hout)[warp * 32 + lane] = o;
}

// ---------------------------------------------------------------------------
// out[i] = normalize(h[x[i]])  -- one warp per (b,t)
// ---------------------------------------------------------------------------
__global__ void k_output(const float* __restrict__ h,
                         const int* __restrict__ x,
                         float* __restrict__ out) {
    int warp = (blockIdx.x * blockDim.x + threadIdx.x) >> 5;
    int lane = threadIdx.x & 31;
    if (warp >= BT) return;
    int idx = x[warp];
    float4 v = ((const float4*)h)[idx * 32 + lane];
    float ss = v.x * v.x + v.y * v.y + v.z * v.z + v.w * v.w;
    #pragma unroll
    for (int o = 16; o; o >>= 1) ss += __shfl_xor_sync(0xffffffffu, ss, o);
    float inv = 1.f / fmaxf(sqrtf(ss), 1e-5f);
    ((float4*)out)[warp * 32 + lane] =
        make_float4(v.x * inv, v.y * inv, v.z * inv, v.w * inv);
}

// ---------------------------------------------------------------------------
// host launch
// ---------------------------------------------------------------------------
extern "C" void kernel_launch(void* const* d_in, const int* in_sizes, int n_in,
                              void* d_out, int out_size) {
    const float* emb = (const float*)d_in[0];
    const float* W0  = (const float*)d_in[1];
    const float* al0 = (const float*)d_in[2];
    const float* ar0 = (const float*)d_in[3];
    const float* b0  = (const float*)d_in[4];
    const float* W1  = (const float*)d_in[5];
    const float* al1 = (const float*)d_in[6];
    const float* ar1 = (const float*)d_in[7];
    const float* b1  = (const float*)d_in[8];
    const int*   nf  = (const int*)d_in[9];
    const int*   src = (const int*)d_in[10];
    const int*   dst = (const int*)d_in[11];
    const int*   x   = (const int*)d_in[12];
    float* out = (float*)d_out;

    float *h0, *h1, *z, *el, *er;
    int *cnt;
    cudaGetSymbolAddress((void**)&h0, g_h0);
    cudaGetSymbolAddress((void**)&h1, g_h1);
    cudaGetSymbolAddress((void**)&z,  g_z);
    cudaGetSymbolAddress((void**)&el, g_el);
    cudaGetSymbolAddress((void**)&er, g_er);
    cudaGetSymbolAddress((void**)&cnt, g_cnt);

    const int T = 256;
    int gbCount  = (EE / 4 + T - 1) / T;
    int gbE      = (EE + T - 1) / T;
    int gbGemm   = (NN + 63) / 64;
    int gbScores = (NN * 8 + T - 1) / T;
    int gbAgg    = (NN * 32 + T - 1) / T;
    int gbOut    = (BT * 32 + T - 1) / T;

    // CSR build (same graph for both layers)
    cudaMemsetAsync(cnt, 0, NPAD * sizeof(int));
    k_count<<<gbCount, T>>>((const int4*)dst);
    k_scan<<<1, 1024>>>();
    cudaMemsetAsync(cnt, 0, NPAD * sizeof(int));
    k_scatter<<<gbE, T>>>(src, dst);

    // layer 0 (fused embedding gather in GEMM; activation on)
    k_gemm<<<gbGemm, 128>>>(emb, nf, W0, z, h0);
    k_scores<<<gbScores, T>>>(z, al0, ar0, el, er);
    k_aggregate<<<gbAgg, T>>>(z, el, er, h0, b0, h1, 1);

    // layer 1 (no activation)
    k_gemm<<<gbGemm, 128>>>(h1, nullptr, W1, z, nullptr);
    k_scores<<<gbScores, T>>>(z, al1, ar1, el, er);
    k_aggregate<<<gbAgg, T>>>(z, el, er, h1, b1, h0, 0);

    // normalize + final gather
    k_output<<<gbOut, T>>>(h0, x, out);
}

// round 3
// speedup vs baseline: 1.1782x; 1.1782x over previous
#include <cuda_runtime.h>

// ---- problem constants (hardcoded in reference module) ----
#define NN 57254
#define EE 916064
#define NPAD 57344           // 1024*56, padded counter array
#define BT 32768             // B*T

// ---- device scratch (static: no allocation allowed) ----
__device__ float g_h0[NN * 128];
__device__ float g_h1[NN * 128];
__device__ float g_z [NN * 128];
__device__ float g_el[NN * 8];
__device__ float g_er[NN * 8];
__device__ int   g_rowptr[NN + 1];
__device__ int   g_cnt[NPAD];
__device__ int   g_csrc[EE];

// ---------------------------------------------------------------------------
// CSR build: count (int4), single-block 2-pass scan, scatter
// ---------------------------------------------------------------------------
__global__ void k_count(const int4* __restrict__ dst4) {
    int i = blockIdx.x * blockDim.x + threadIdx.x;
    if (i < EE / 4) {
        int4 d = dst4[i];
        atomicAdd(&g_cnt[d.x], 1);
        atomicAdd(&g_cnt[d.y], 1);
        atomicAdd(&g_cnt[d.z], 1);
        atomicAdd(&g_cnt[d.w], 1);
    }
}

__global__ __launch_bounds__(1024) void k_scan() {
    __shared__ int wsum[32];
    int t = threadIdx.x;
    int lane = t & 31, wid = t >> 5;
    const int4* c4 = (const int4*)g_cnt;

    int tot = 0;
    #pragma unroll
    for (int j = 0; j < 14; j++) {
        int4 v = c4[t * 14 + j];
        tot += v.x + v.y + v.z + v.w;
    }
    int s = tot;
    #pragma unroll
    for (int o = 1; o < 32; o <<= 1) {
        int u = __shfl_up_sync(0xffffffffu, s, o);
        if (lane >= o) s += u;
    }
    if (lane == 31) wsum[wid] = s;
    __syncthreads();
    if (wid == 0) {
        int wv = wsum[lane];
        #pragma unroll
        for (int o = 1; o < 32; o <<= 1) {
            int u = __shfl_up_sync(0xffffffffu, wv, o);
            if (lane >= o) wv += u;
        }
        wsum[lane] = wv;
    }
    __syncthreads();
    int run = s - tot + (wid > 0 ? wsum[wid - 1] : 0);

    #pragma unroll
    for (int j = 0; j < 14; j++) {
        int4 v = c4[t * 14 + j];
        int idx = t * 56 + j * 4;
        if (idx + 3 < NN) {
            int4 o;
            o.x = run;             o.y = run + v.x;
            o.z = run + v.x + v.y; o.w = run + v.x + v.y + v.z;
            *(int4*)(g_rowptr + idx) = o;
            run += v.x + v.y + v.z + v.w;
        } else {
            if (idx     < NN) g_rowptr[idx]     = run; run += v.x;
            if (idx + 1 < NN) g_rowptr[idx + 1] = run; run += v.y;
            if (idx + 2 < NN) g_rowptr[idx + 2] = run; run += v.z;
            if (idx + 3 < NN) g_rowptr[idx + 3] = run; run += v.w;
        }
    }
    if (t == 1023) g_rowptr[NN] = EE;
}

__global__ void k_scatter(const int* __restrict__ src, const int* __restrict__ dst) {
    int i = blockIdx.x * blockDim.x + threadIdx.x;
    if (i >= EE) return;
    int d = dst[i];
    int pos = g_rowptr[d] + atomicAdd(&g_cnt[d], 1);
    g_csrc[pos] = src[i];
}

// ---------------------------------------------------------------------------
// tf32 tensor-core GEMM: z = h @ W  (NNx128 @ 128x128).
// Block tile 128x128, 128 threads (4 warps, 2x2), warp tile 64x64
// (4 m-tiles x 8 n-tiles of m16n8k8), K-chunks of 32.
// Optional fused gather: nf != null -> rows from emb[nf[r]], also writes hout.
// ---------------------------------------------------------------------------
__device__ __forceinline__ unsigned f2tf(float f) {
    unsigned u;
    asm("cvt.rna.tf32.f32 %0, %1;" : "=r"(u) : "f"(f));
    return u;
}

__device__ __forceinline__ void mma8(float* c, const unsigned* a,
                                     unsigned b0, unsigned b1) {
    asm volatile(
        "mma.sync.aligned.m16n8k8.row.col.f32.tf32.tf32.f32 "
        "{%0,%1,%2,%3},{%4,%5,%6,%7},{%8,%9},{%0,%1,%2,%3};"
        : "+f"(c[0]), "+f"(c[1]), "+f"(c[2]), "+f"(c[3])
        : "r"(a[0]), "r"(a[1]), "r"(a[2]), "r"(a[3]), "r"(b0), "r"(b1));
}

#define SA_STRIDE 36
#define SB_STRIDE 136

__global__ __launch_bounds__(128) void k_gemm(const float* __restrict__ hsrc,
                                              const int* __restrict__ nf,
                                              const float* __restrict__ W,
                                              float* __restrict__ z,
                                              float* __restrict__ hout) {
    __shared__ unsigned sA[128 * SA_STRIDE];
    __shared__ unsigned sB[32 * SB_STRIDE];
    __shared__ int srow[128];

    int t = threadIdx.x;
    int rowbase = blockIdx.x * 128;
    {
        int r = rowbase + t;
        srow[t] = (r < NN) ? (nf ? nf[r] : r) : -1;
    }
    __syncthreads();

    int warp = t >> 5, lane = t & 31;
    int qr = lane >> 2, qc = lane & 3;
    int wm = (warp >> 1) * 64;     // warp row offset in tile
    int wn = (warp & 1) * 64;      // warp col offset

    float c[4][8][4];
    #pragma unroll
    for (int mt = 0; mt < 4; mt++)
        #pragma unroll
        for (int nt = 0; nt < 8; nt++)
            #pragma unroll
            for (int i = 0; i < 4; i++) c[mt][nt][i] = 0.f;

    for (int kb = 0; kb < 128; kb += 32) {
        // stage A (128x32) with tf32 convert; fused gather/hout on layer 0
        #pragma unroll
        for (int j = 0; j < 8; j++) {
            int idx = t + j * 128;        // 0..1023 float4 slots
            int row = idx >> 3, kq = idx & 7;
            int sidx = srow[row];
            float4 v = make_float4(0.f, 0.f, 0.f, 0.f);
            if (sidx >= 0) v = *(const float4*)(hsrc + (long)sidx * 128 + kb + kq * 4);
            if (hout != nullptr && sidx >= 0)
                *(float4*)(hout + (long)(rowbase + row) * 128 + kb + kq * 4) = v;
            uint4 u = make_uint4(f2tf(v.x), f2tf(v.y), f2tf(v.z), f2tf(v.w));
            *(uint4*)(sA + row * SA_STRIDE + kq * 4) = u;
        }
        // stage B = W chunk (32x128)
        #pragma unroll
        for (int j = 0; j < 8; j++) {
            int idx = t + j * 128;
            int kr = idx >> 5, c4i = idx & 31;
            float4 v = *(const float4*)(W + (long)(kb + kr) * 128 + c4i * 4);
            uint4 u = make_uint4(f2tf(v.x), f2tf(v.y), f2tf(v.z), f2tf(v.w));
            *(uint4*)(sB + kr * SB_STRIDE + c4i * 4) = u;
        }
        __syncthreads();

        #pragma unroll
        for (int kk = 0; kk < 4; kk++) {
            unsigned a[4][4];
            #pragma unroll
            for (int mt = 0; mt < 4; mt++) {
                int r = wm + mt * 16 + qr;
                a[mt][0] = sA[(r)     * SA_STRIDE + kk * 8 + qc];
                a[mt][1] = sA[(r + 8) * SA_STRIDE + kk * 8 + qc];
                a[mt][2] = sA[(r)     * SA_STRIDE + kk * 8 + qc + 4];
                a[mt][3] = sA[(r + 8) * SA_STRIDE + kk * 8 + qc + 4];
            }
            #pragma unroll
            for (int nt = 0; nt < 8; nt++) {
                int col = wn + nt * 8 + qr;
                unsigned b0 = sB[(kk * 8 + qc)     * SB_STRIDE + col];
                unsigned b1 = sB[(kk * 8 + qc + 4) * SB_STRIDE + col];
                #pragma unroll
                for (int mt = 0; mt < 4; mt++) mma8(c[mt][nt], a[mt], b0, b1);
            }
        }
        __syncthreads();
    }

    // epilogue: c0,c1 -> (row, col..col+1); c2,c3 -> (row+8, ...)
    #pragma unroll
    for (int mt = 0; mt < 4; mt++) {
        int r0 = rowbase + wm + mt * 16 + qr;
        int r1 = r0 + 8;
        #pragma unroll
        for (int nt = 0; nt < 8; nt++) {
            int col = wn + nt * 8 + qc * 2;
            if (r0 < NN)
                *(float2*)(z + (long)r0 * 128 + col) = make_float2(c[mt][nt][0], c[mt][nt][1]);
            if (r1 < NN)
                *(float2*)(z + (long)r1 * 128 + col) = make_float2(c[mt][nt][2], c[mt][nt][3]);
        }
    }
}

// ---------------------------------------------------------------------------
// el[n,h] = sum_o z[n,h,o]*al[h,o];  er likewise
// ---------------------------------------------------------------------------
__global__ void k_scores(const float* __restrict__ z,
                         const float* __restrict__ al,
                         const float* __restrict__ ar,
                         float* __restrict__ el,
                         float* __restrict__ er) {
    int i = blockIdx.x * blockDim.x + threadIdx.x;
    if (i >= NN * 8) return;
    int n = i >> 3, hd = i & 7;
    const float4* zp  = (const float4*)(z + (long)n * 128 + hd * 16);
    const float4* alp = (const float4*)(al + hd * 16);
    const float4* arp = (const float4*)(ar + hd * 16);
    float sl = 0.f, sr = 0.f;
    #pragma unroll
    for (int j = 0; j < 4; j++) {
        float4 zz = zp[j], a = alp[j], r = arp[j];
        sl += zz.x * a.x + zz.y * a.y + zz.z * a.z + zz.w * a.w;
        sr += zz.x * r.x + zz.y * r.y + zz.z * r.z + zz.w * r.w;
    }
    el[i] = sl;
    er[i] = sr;
}

// ---------------------------------------------------------------------------
// Per-dst edge softmax + aggregate + residual + bias (+ leaky_relu).
// One warp/node, 4-edge software pipeline for MLP.
// ---------------------------------------------------------------------------
__global__ __launch_bounds__(256) void k_aggregate(const float* __restrict__ z,
                                                   const float* __restrict__ el,
                                                   const float* __restrict__ er,
                                                   const float* __restrict__ hin,
                                                   const float* __restrict__ bias,
                                                   float* __restrict__ hout,
                                                   int activate) {
    int warp = (blockIdx.x * blockDim.x + threadIdx.x) >> 5;
    int lane = threadIdx.x & 31;
    if (warp >= NN) return;
    int hd = lane >> 2;
    float erh = er[warp * 8 + hd];
    int beg = g_rowptr[warp], end = g_rowptr[warp + 1];
    const float4* z4 = (const float4*)z;
    float s = 0.f;
    float4 acc = make_float4(0.f, 0.f, 0.f, 0.f);

    int e = beg;
    for (; e + 4 <= end; e += 4) {
        int s0 = g_csrc[e],     s1 = g_csrc[e + 1];
        int s2 = g_csrc[e + 2], s3 = g_csrc[e + 3];
        float x0 = el[s0 * 8 + hd], x1 = el[s1 * 8 + hd];
        float x2 = el[s2 * 8 + hd], x3 = el[s3 * 8 + hd];
        float4 za = z4[s0 * 32 + lane], zb = z4[s1 * 32 + lane];
        float4 zc = z4[s2 * 32 + lane], zd = z4[s3 * 32 + lane];
        x0 += erh; x0 = x0 > 0.f ? x0 : 0.2f * x0; float a0 = __expf(x0);
        x1 += erh; x1 = x1 > 0.f ? x1 : 0.2f * x1; float a1 = __expf(x1);
        x2 += erh; x2 = x2 > 0.f ? x2 : 0.2f * x2; float a2 = __expf(x2);
        x3 += erh; x3 = x3 > 0.f ? x3 : 0.2f * x3; float a3 = __expf(x3);
        s += a0; acc.x += a0 * za.x; acc.y += a0 * za.y; acc.z += a0 * za.z; acc.w += a0 * za.w;
        s += a1; acc.x += a1 * zb.x; acc.y += a1 * zb.y; acc.z += a1 * zb.z; acc.w += a1 * zb.w;
        s += a2; acc.x += a2 * zc.x; acc.y += a2 * zc.y; acc.z += a2 * zc.z; acc.w += a2 * zc.w;
        s += a3; acc.x += a3 * zd.x; acc.y += a3 * zd.y; acc.z += a3 * zd.z; acc.w += a3 * zd.w;
    }
    for (; e < end; e++) {
        int sr = g_csrc[e];
        float x = el[sr * 8 + hd] + erh;
        x = x > 0.f ? x : 0.2f * x;
        float a = __expf(x);
        s += a;
        float4 zz = z4[sr * 32 + lane];
        acc.x += a * zz.x; acc.y += a * zz.y;
        acc.z += a * zz.z; acc.w += a * zz.w;
    }
    float inv = (s > 0.f) ? (1.f / s) : 0.f;
    float4 hv = ((const float4*)hin)[warp * 32 + lane];
    float4 bv = ((const float4*)bias)[lane];
    float4 o;
    o.x = acc.x * inv + hv.x + bv.x;
    o.y = acc.y * inv + hv.y + bv.y;
    o.z = acc.z * inv + hv.z + bv.z;
    o.w = acc.w * inv + hv.w + bv.w;
    if (activate) {
        o.x = o.x > 0.f ? o.x : 0.01f * o.x;
        o.y = o.y > 0.f ? o.y : 0.01f * o.y;
        o.z = o.z > 0.f ? o.z : 0.01f * o.z;
        o.w = o.w > 0.f ? o.w : 0.01f * o.w;
    }
    ((float4*)hout)[warp * 32 + lane] = o;
}

// ---------------------------------------------------------------------------
// out[i] = normalize(h[x[i]])  -- one warp per (b,t)
// ---------------------------------------------------------------------------
__global__ void k_output(const float* __restrict__ h,
                         const int* __restrict__ x,
                         float* __restrict__ out) {
    int warp = (blockIdx.x * blockDim.x + threadIdx.x) >> 5;
    int lane = threadIdx.x & 31;
    if (warp >= BT) return;
    int idx = x[warp];
    float4 v = ((const float4*)h)[idx * 32 + lane];
    float ss = v.x * v.x + v.y * v.y + v.z * v.z + v.w * v.w;
    #pragma unroll
    for (int o = 16; o; o >>= 1) ss += __shfl_xor_sync(0xffffffffu, ss, o);
    float inv = 1.f / fmaxf(sqrtf(ss), 1e-5f);
    ((float4*)out)[warp * 32 + lane] =
        make_float4(v.x * inv, v.y * inv, v.z * inv, v.w * inv);
}

// ---------------------------------------------------------------------------
// host launch
// ---------------------------------------------------------------------------
extern "C" void kernel_launch(void* const* d_in, const int* in_sizes, int n_in,
                              void* d_out, int out_size) {
    const float* emb = (const float*)d_in[0];
    const float* W0  = (const float*)d_in[1];
    const float* al0 = (const float*)d_in[2];
    const float* ar0 = (const float*)d_in[3];
    const float* b0  = (const float*)d_in[4];
    const float* W1  = (const float*)d_in[5];
    const float* al1 = (const float*)d_in[6];
    const float* ar1 = (const float*)d_in[7];
    const float* b1  = (const float*)d_in[8];
    const int*   nf  = (const int*)d_in[9];
    const int*   src = (const int*)d_in[10];
    const int*   dst = (const int*)d_in[11];
    const int*   x   = (const int*)d_in[12];
    float* out = (float*)d_out;

    float *h0, *h1, *z, *el, *er;
    int *cnt;
    cudaGetSymbolAddress((void**)&h0, g_h0);
    cudaGetSymbolAddress((void**)&h1, g_h1);
    cudaGetSymbolAddress((void**)&z,  g_z);
    cudaGetSymbolAddress((void**)&el, g_el);
    cudaGetSymbolAddress((void**)&er, g_er);
    cudaGetSymbolAddress((void**)&cnt, g_cnt);

    const int T = 256;
    int gbCount  = (EE / 4 + T - 1) / T;
    int gbE      = (EE + T - 1) / T;
    int gbGemm   = (NN + 127) / 128;
    int gbScores = (NN * 8 + T - 1) / T;
    int gbAgg    = (NN * 32 + T - 1) / T;
    int gbOut    = (BT * 32 + T - 1) / T;

    // CSR build (same graph for both layers)
    cudaMemsetAsync(cnt, 0, NPAD * sizeof(int));
    k_count<<<gbCount, T>>>((const int4*)dst);
    k_scan<<<1, 1024>>>();
    cudaMemsetAsync(cnt, 0, NPAD * sizeof(int));
    k_scatter<<<gbE, T>>>(src, dst);

    // layer 0 (fused embedding gather in GEMM; activation on)
    k_gemm<<<gbGemm, 128>>>(emb, nf, W0, z, h0);
    k_scores<<<gbScores, T>>>(z, al0, ar0, el, er);
    k_aggregate<<<gbAgg, T>>>(z, el, er, h0, b0, h1, 1);

    // layer 1 (no activation)
    k_gemm<<<gbGemm, 128>>>(h1, nullptr, W1, z, nullptr);
    k_scores<<<gbScores, T>>>(z, al1, ar1, el, er);
    k_aggregate<<<gbAgg, T>>>(z, el, er, h1, b1, h0, 0);

    // normalize + final gather
    k_output<<<gbOut, T>>>(h0, x, out);
}

// round 4
// speedup vs baseline: 1.4204x; 1.2056x over previous
#include <cuda_runtime.h>

// ---- problem constants (hardcoded in reference module) ----
#define NN 57254
#define EE 916064
#define NPAD 57344           // 1024*56, padded counter array
#define BT 32768             // B*T

// ---- device scratch (static: no allocation allowed) ----
__device__ float g_h0[NN * 128];
__device__ float g_h1[NN * 128];
__device__ float g_z [NN * 128];
__device__ float g_el[NN * 8];
__device__ float g_er[NN * 8];
__device__ int   g_rowptr[NN + 1];
__device__ int   g_cnt[NPAD];
__device__ int   g_csrc[EE];

// ---------------------------------------------------------------------------
// CSR build: count (int4), single-block 2-pass scan, scatter
// ---------------------------------------------------------------------------
__global__ void k_count(const int4* __restrict__ dst4) {
    int i = blockIdx.x * blockDim.x + threadIdx.x;
    if (i < EE / 4) {
        int4 d = dst4[i];
        atomicAdd(&g_cnt[d.x], 1);
        atomicAdd(&g_cnt[d.y], 1);
        atomicAdd(&g_cnt[d.z], 1);
        atomicAdd(&g_cnt[d.w], 1);
    }
}

__global__ __launch_bounds__(1024) void k_scan() {
    __shared__ int wsum[32];
    int t = threadIdx.x;
    int lane = t & 31, wid = t >> 5;
    const int4* c4 = (const int4*)g_cnt;

    int tot = 0;
    #pragma unroll
    for (int j = 0; j < 14; j++) {
        int4 v = c4[t * 14 + j];
        tot += v.x + v.y + v.z + v.w;
    }
    int s = tot;
    #pragma unroll
    for (int o = 1; o < 32; o <<= 1) {
        int u = __shfl_up_sync(0xffffffffu, s, o);
        if (lane >= o) s += u;
    }
    if (lane == 31) wsum[wid] = s;
    __syncthreads();
    if (wid == 0) {
        int wv = wsum[lane];
        #pragma unroll
        for (int o = 1; o < 32; o <<= 1) {
            int u = __shfl_up_sync(0xffffffffu, wv, o);
            if (lane >= o) wv += u;
        }
        wsum[lane] = wv;
    }
    __syncthreads();
    int run = s - tot + (wid > 0 ? wsum[wid - 1] : 0);

    #pragma unroll
    for (int j = 0; j < 14; j++) {
        int4 v = c4[t * 14 + j];
        int idx = t * 56 + j * 4;
        if (idx + 3 < NN) {
            int4 o;
            o.x = run;             o.y = run + v.x;
            o.z = run + v.x + v.y; o.w = run + v.x + v.y + v.z;
            *(int4*)(g_rowptr + idx) = o;
            run += v.x + v.y + v.z + v.w;
        } else {
            if (idx     < NN) g_rowptr[idx]     = run; run += v.x;
            if (idx + 1 < NN) g_rowptr[idx + 1] = run; run += v.y;
            if (idx + 2 < NN) g_rowptr[idx + 2] = run; run += v.z;
            if (idx + 3 < NN) g_rowptr[idx + 3] = run; run += v.w;
        }
    }
    if (t == 1023) g_rowptr[NN] = EE;
}

__global__ void k_scatter(const int* __restrict__ src, const int* __restrict__ dst) {
    int i = blockIdx.x * blockDim.x + threadIdx.x;
    if (i >= EE) return;
    int d = dst[i];
    int pos = g_rowptr[d] + atomicAdd(&g_cnt[d], 1);
    g_csrc[pos] = src[i];
}

// ---------------------------------------------------------------------------
// tf32 tensor-core GEMM: z = h @ W  (NNx128 @ 128x128).
// Block tile 128x128, 256 threads (8 warps 4x2), warp tile 32x64
// (2 m-tiles x 8 n-tiles m16n8k8). K-chunks of 32 with REGISTER PREFETCH:
// next chunk's global loads issue before current chunk's mma work.
// Optional fused gather: nf != null -> rows from emb[nf[r]], also writes hout.
// ---------------------------------------------------------------------------
__device__ __forceinline__ unsigned f2tf(float f) {
    unsigned u;
    asm("cvt.rna.tf32.f32 %0, %1;" : "=r"(u) : "f"(f));
    return u;
}

__device__ __forceinline__ void mma8(float* c, const unsigned* a,
                                     unsigned b0, unsigned b1) {
    asm volatile(
        "mma.sync.aligned.m16n8k8.row.col.f32.tf32.tf32.f32 "
        "{%0,%1,%2,%3},{%4,%5,%6,%7},{%8,%9},{%0,%1,%2,%3};"
        : "+f"(c[0]), "+f"(c[1]), "+f"(c[2]), "+f"(c[3])
        : "r"(a[0]), "r"(a[1]), "r"(a[2]), "r"(a[3]), "r"(b0), "r"(b1));
}

#define SA_STRIDE 36
#define SB_STRIDE 136

__global__ __launch_bounds__(256) void k_gemm(const float* __restrict__ hsrc,
                                              const int* __restrict__ nf,
                                              const float* __restrict__ W,
                                              float* __restrict__ z,
                                              float* __restrict__ hout) {
    __shared__ unsigned sA[128 * SA_STRIDE];   // 18.4 KB
    __shared__ unsigned sB[32 * SB_STRIDE];    // 17.4 KB
    __shared__ int srow[128];

    int t = threadIdx.x;
    int rowbase = blockIdx.x * 128;
    if (t < 128) {
        int r = rowbase + t;
        srow[t] = (r < NN) ? (nf ? nf[r] : r) : -1;
    }
    __syncthreads();

    int warp = t >> 5, lane = t & 31;
    int qr = lane >> 2, qc = lane & 3;
    int wm = (warp >> 1) * 32;     // 4 row-groups of 32
    int wn = (warp & 1) * 64;      // 2 col-groups of 64

    // per-thread staging coordinates (4 float4 slots each for A and B)
    int arow[4], akq[4], bkr[4], bc4[4], asid[4];
    #pragma unroll
    for (int j = 0; j < 4; j++) {
        int idx = t + j * 256;          // 0..1023
        arow[j] = idx >> 3;  akq[j] = idx & 7;
        bkr[j]  = idx >> 5;  bc4[j] = idx & 31;
        asid[j] = srow[arow[j]];
    }

    float c[2][8][4];
    #pragma unroll
    for (int mt = 0; mt < 2; mt++)
        #pragma unroll
        for (int nt = 0; nt < 8; nt++)
            #pragma unroll
            for (int i = 0; i < 4; i++) c[mt][nt][i] = 0.f;

    float4 av[4], bv[4];

    // ---- load chunk 0 ----
    #pragma unroll
    for (int j = 0; j < 4; j++) {
        av[j] = make_float4(0.f, 0.f, 0.f, 0.f);
        if (asid[j] >= 0)
            av[j] = *(const float4*)(hsrc + (long)asid[j] * 128 + akq[j] * 4);
        bv[j] = *(const float4*)(W + (long)bkr[j] * 128 + bc4[j] * 4);
    }
    if (hout != nullptr) {
        #pragma unroll
        for (int j = 0; j < 4; j++)
            if (asid[j] >= 0)
                *(float4*)(hout + (long)(rowbase + arow[j]) * 128 + akq[j] * 4) = av[j];
    }
    #pragma unroll
    for (int j = 0; j < 4; j++) {
        *(uint4*)(sA + arow[j] * SA_STRIDE + akq[j] * 4) =
            make_uint4(f2tf(av[j].x), f2tf(av[j].y), f2tf(av[j].z), f2tf(av[j].w));
        *(uint4*)(sB + bkr[j] * SB_STRIDE + bc4[j] * 4) =
            make_uint4(f2tf(bv[j].x), f2tf(bv[j].y), f2tf(bv[j].z), f2tf(bv[j].w));
    }
    __syncthreads();

    #pragma unroll
    for (int kb = 0; kb < 4; kb++) {
        // ---- prefetch chunk kb+1 into registers (hides gmem latency) ----
        if (kb < 3) {
            int ko = (kb + 1) * 32;
            #pragma unroll
            for (int j = 0; j < 4; j++) {
                av[j] = make_float4(0.f, 0.f, 0.f, 0.f);
                if (asid[j] >= 0)
                    av[j] = *(const float4*)(hsrc + (long)asid[j] * 128 + ko + akq[j] * 4);
                bv[j] = *(const float4*)(W + (long)(ko + bkr[j]) * 128 + bc4[j] * 4);
            }
        }

        // ---- compute current chunk ----
        #pragma unroll
        for (int kk = 0; kk < 4; kk++) {
            unsigned a[2][4];
            #pragma unroll
            for (int mt = 0; mt < 2; mt++) {
                int r = wm + mt * 16 + qr;
                a[mt][0] = sA[(r)      * SA_STRIDE + kk * 8 + qc];
                a[mt][1] = sA[(r + 8)  * SA_STRIDE + kk * 8 + qc];
                a[mt][2] = sA[(r)      * SA_STRIDE + kk * 8 + qc + 4];
                a[mt][3] = sA[(r + 8)  * SA_STRIDE + kk * 8 + qc + 4];
            }
            #pragma unroll
            for (int nt = 0; nt < 8; nt++) {
                int col = wn + nt * 8 + qr;
                unsigned b0 = sB[(kk * 8 + qc)     * SB_STRIDE + col];
                unsigned b1 = sB[(kk * 8 + qc + 4) * SB_STRIDE + col];
                #pragma unroll
                for (int mt = 0; mt < 2; mt++) mma8(c[mt][nt], a[mt], b0, b1);
            }
        }

        // ---- commit prefetched chunk to smem ----
        if (kb < 3) {
            int ko = (kb + 1) * 32;
            __syncthreads();      // all warps done reading current chunk
            if (hout != nullptr) {
                #pragma unroll
                for (int j = 0; j < 4; j++)
                    if (asid[j] >= 0)
                        *(float4*)(hout + (long)(rowbase + arow[j]) * 128 + ko + akq[j] * 4) = av[j];
            }
            #pragma unroll
            for (int j = 0; j < 4; j++) {
                *(uint4*)(sA + arow[j] * SA_STRIDE + akq[j] * 4) =
                    make_uint4(f2tf(av[j].x), f2tf(av[j].y), f2tf(av[j].z), f2tf(av[j].w));
                *(uint4*)(sB + bkr[j] * SB_STRIDE + bc4[j] * 4) =
                    make_uint4(f2tf(bv[j].x), f2tf(bv[j].y), f2tf(bv[j].z), f2tf(bv[j].w));
            }
            __syncthreads();
        }
    }

    // ---- epilogue ----
    #pragma unroll
    for (int mt = 0; mt < 2; mt++) {
        int r0 = rowbase + wm + mt * 16 + qr;
        int r1 = r0 + 8;
        #pragma unroll
        for (int nt = 0; nt < 8; nt++) {
            int col = wn + nt * 8 + qc * 2;
            if (r0 < NN)
                *(float2*)(z + (long)r0 * 128 + col) = make_float2(c[mt][nt][0], c[mt][nt][1]);
            if (r1 < NN)
                *(float2*)(z + (long)r1 * 128 + col) = make_float2(c[mt][nt][2], c[mt][nt][3]);
        }
    }
}

// ---------------------------------------------------------------------------
// el[n,h] = sum_o z[n,h,o]*al[h,o];  er likewise
// ---------------------------------------------------------------------------
__global__ void k_scores(const float* __restrict__ z,
                         const float* __restrict__ al,
                         const float* __restrict__ ar,
                         float* __restrict__ el,
                         float* __restrict__ er) {
    int i = blockIdx.x * blockDim.x + threadIdx.x;
    if (i >= NN * 8) return;
    int n = i >> 3, hd = i & 7;
    const float4* zp  = (const float4*)(z + (long)n * 128 + hd * 16);
    const float4* alp = (const float4*)(al + hd * 16);
    const float4* arp = (const float4*)(ar + hd * 16);
    float sl = 0.f, sr = 0.f;
    #pragma unroll
    for (int j = 0; j < 4; j++) {
        float4 zz = zp[j], a = alp[j], r = arp[j];
        sl += zz.x * a.x + zz.y * a.y + zz.z * a.z + zz.w * a.w;
        sr += zz.x * r.x + zz.y * r.y + zz.z * r.z + zz.w * r.w;
    }
    el[i] = sl;
    er[i] = sr;
}

// ---------------------------------------------------------------------------
// Per-dst edge softmax + aggregate + residual + bias (+ leaky_relu).
// One warp/node, 4-edge software pipeline for MLP.
// ---------------------------------------------------------------------------
__global__ __launch_bounds__(256) void k_aggregate(const float* __restrict__ z,
                                                   const float* __restrict__ el,
                                                   const float* __restrict__ er,
                                                   const float* __restrict__ hin,
                                                   const float* __restrict__ bias,
                                                   float* __restrict__ hout,
                                                   int activate) {
    int warp = (blockIdx.x * blockDim.x + threadIdx.x) >> 5;
    int lane = threadIdx.x & 31;
    if (warp >= NN) return;
    int hd = lane >> 2;
    float erh = er[warp * 8 + hd];
    int beg = g_rowptr[warp], end = g_rowptr[warp + 1];
    const float4* z4 = (const float4*)z;
    float s = 0.f;
    float4 acc = make_float4(0.f, 0.f, 0.f, 0.f);

    int e = beg;
    for (; e + 4 <= end; e += 4) {
        int s0 = g_csrc[e],     s1 = g_csrc[e + 1];
        int s2 = g_csrc[e + 2], s3 = g_csrc[e + 3];
        float x0 = el[s0 * 8 + hd], x1 = el[s1 * 8 + hd];
        float x2 = el[s2 * 8 + hd], x3 = el[s3 * 8 + hd];
        float4 za = z4[s0 * 32 + lane], zb = z4[s1 * 32 + lane];
        float4 zc = z4[s2 * 32 + lane], zd = z4[s3 * 32 + lane];
        x0 += erh; x0 = x0 > 0.f ? x0 : 0.2f * x0; float a0 = __expf(x0);
        x1 += erh; x1 = x1 > 0.f ? x1 : 0.2f * x1; float a1 = __expf(x1);
        x2 += erh; x2 = x2 > 0.f ? x2 : 0.2f * x2; float a2 = __expf(x2);
        x3 += erh; x3 = x3 > 0.f ? x3 : 0.2f * x3; float a3 = __expf(x3);
        s += a0; acc.x += a0 * za.x; acc.y += a0 * za.y; acc.z += a0 * za.z; acc.w += a0 * za.w;
        s += a1; acc.x += a1 * zb.x; acc.y += a1 * zb.y; acc.z += a1 * zb.z; acc.w += a1 * zb.w;
        s += a2; acc.x += a2 * zc.x; acc.y += a2 * zc.y; acc.z += a2 * zc.z; acc.w += a2 * zc.w;
        s += a3; acc.x += a3 * zd.x; acc.y += a3 * zd.y; acc.z += a3 * zd.z; acc.w += a3 * zd.w;
    }
    for (; e < end; e++) {
        int sr = g_csrc[e];
        float x = el[sr * 8 + hd] + erh;
        x = x > 0.f ? x : 0.2f * x;
        float a = __expf(x);
        s += a;
        float4 zz = z4[sr * 32 + lane];
        acc.x += a * zz.x; acc.y += a * zz.y;
        acc.z += a * zz.z; acc.w += a * zz.w;
    }
    float inv = (s > 0.f) ? (1.f / s) : 0.f;
    float4 hv = ((const float4*)hin)[warp * 32 + lane];
    float4 bv = ((const float4*)bias)[lane];
    float4 o;
    o.x = acc.x * inv + hv.x + bv.x;
    o.y = acc.y * inv + hv.y + bv.y;
    o.z = acc.z * inv + hv.z + bv.z;
    o.w = acc.w * inv + hv.w + bv.w;
    if (activate) {
        o.x = o.x > 0.f ? o.x : 0.01f * o.x;
        o.y = o.y > 0.f ? o.y : 0.01f * o.y;
        o.z = o.z > 0.f ? o.z : 0.01f * o.z;
        o.w = o.w > 0.f ? o.w : 0.01f * o.w;
    }
    ((float4*)hout)[warp * 32 + lane] = o;
}

// ---------------------------------------------------------------------------
// out[i] = normalize(h[x[i]])  -- one warp per (b,t)
// ---------------------------------------------------------------------------
__global__ void k_output(const float* __restrict__ h,
                         const int* __restrict__ x,
                         float* __restrict__ out) {
    int warp = (blockIdx.x * blockDim.x + threadIdx.x) >> 5;
    int lane = threadIdx.x & 31;
    if (warp >= BT) return;
    int idx = x[warp];
    float4 v = ((const float4*)h)[idx * 32 + lane];
    float ss = v.x * v.x + v.y * v.y + v.z * v.z + v.w * v.w;
    #pragma unroll
    for (int o = 16; o; o >>= 1) ss += __shfl_xor_sync(0xffffffffu, ss, o);
    float inv = 1.f / fmaxf(sqrtf(ss), 1e-5f);
    ((float4*)out)[warp * 32 + lane] =
        make_float4(v.x * inv, v.y * inv, v.z * inv, v.w * inv);
}

// ---------------------------------------------------------------------------
// host launch
// ---------------------------------------------------------------------------
extern "C" void kernel_launch(void* const* d_in, const int* in_sizes, int n_in,
                              void* d_out, int out_size) {
    const float* emb = (const float*)d_in[0];
    const float* W0  = (const float*)d_in[1];
    const float* al0 = (const float*)d_in[2];
    const float* ar0 = (const float*)d_in[3];
    const float* b0  = (const float*)d_in[4];
    const float* W1  = (const float*)d_in[5];
    const float* al1 = (const float*)d_in[6];
    const float* ar1 = (const float*)d_in[7];
    const float* b1  = (const float*)d_in[8];
    const int*   nf  = (const int*)d_in[9];
    const int*   src = (const int*)d_in[10];
    const int*   dst = (const int*)d_in[11];
    const int*   x   = (const int*)d_in[12];
    float* out = (float*)d_out;

    float *h0, *h1, *z, *el, *er;
    int *cnt;
    cudaGetSymbolAddress((void**)&h0, g_h0);
    cudaGetSymbolAddress((void**)&h1, g_h1);
    cudaGetSymbolAddress((void**)&z,  g_z);
    cudaGetSymbolAddress((void**)&el, g_el);
    cudaGetSymbolAddress((void**)&er, g_er);
    cudaGetSymbolAddress((void**)&cnt, g_cnt);

    const int T = 256;
    int gbCount  = (EE / 4 + T - 1) / T;
    int gbE      = (EE + T - 1) / T;
    int gbGemm   = (NN + 127) / 128;
    int gbScores = (NN * 8 + T - 1) / T;
    int gbAgg    = (NN * 32 + T - 1) / T;
    int gbOut    = (BT * 32 + T - 1) / T;

    // CSR build (same graph for both layers)
    cudaMemsetAsync(cnt, 0, NPAD * sizeof(int));
    k_count<<<gbCount, T>>>((const int4*)dst);
    k_scan<<<1, 1024>>>();
    cudaMemsetAsync(cnt, 0, NPAD * sizeof(int));
    k_scatter<<<gbE, T>>>(src, dst);

    // layer 0 (fused embedding gather in GEMM; activation on)
    k_gemm<<<gbGemm, 256>>>(emb, nf, W0, z, h0);
    k_scores<<<gbScores, T>>>(z, al0, ar0, el, er);
    k_aggregate<<<gbAgg, T>>>(z, el, er, h0, b0, h1, 1);

    // layer 1 (no activation)
    k_gemm<<<gbGemm, 256>>>(h1, nullptr, W1, z, nullptr);
    k_scores<<<gbScores, T>>>(z, al1, ar1, el, er);
    k_aggregate<<<gbAgg, T>>>(z, el, er, h1, b1, h0, 0);

    // normalize + final gather
    k_output<<<gbOut, T>>>(h0, x, out);
}

// round 5
// speedup vs baseline: 1.5182x; 1.0688x over previous
#include <cuda_runtime.h>
#include <cuda_fp16.h>

// ---- problem constants (hardcoded in reference module) ----
#define NN 57254
#define EE 916064
#define NPAD 57344           // 1024*56, padded counter array
#define BT 32768             // B*T

// ---- device scratch (static: no allocation allowed) ----
__device__ float  g_h1[NN * 128];
__device__ float  g_hf[NN * 128];
__device__ __half g_z [NN * 128];
__device__ float  g_el[NN * 8];
__device__ float  g_er[NN * 8];
__device__ int    g_rowptr[NN + 1];
__device__ int    g_cnt[NPAD];
__device__ int    g_csrc[EE];

// ---------------------------------------------------------------------------
// CSR build: count (int4), single-block 2-pass scan, scatter
// ---------------------------------------------------------------------------
__global__ void k_count(const int4* __restrict__ dst4) {
    int i = blockIdx.x * blockDim.x + threadIdx.x;
    if (i < EE / 4) {
        int4 d = dst4[i];
        atomicAdd(&g_cnt[d.x], 1);
        atomicAdd(&g_cnt[d.y], 1);
        atomicAdd(&g_cnt[d.z], 1);
        atomicAdd(&g_cnt[d.w], 1);
    }
}

__global__ __launch_bounds__(1024) void k_scan() {
    __shared__ int wsum[32];
    int t = threadIdx.x;
    int lane = t & 31, wid = t >> 5;
    const int4* c4 = (const int4*)g_cnt;

    int tot = 0;
    #pragma unroll
    for (int j = 0; j < 14; j++) {
        int4 v = c4[t * 14 + j];
        tot += v.x + v.y + v.z + v.w;
    }
    int s = tot;
    #pragma unroll
    for (int o = 1; o < 32; o <<= 1) {
        int u = __shfl_up_sync(0xffffffffu, s, o);
        if (lane >= o) s += u;
    }
    if (lane == 31) wsum[wid] = s;
    __syncthreads();
    if (wid == 0) {
        int wv = wsum[lane];
        #pragma unroll
        for (int o = 1; o < 32; o <<= 1) {
            int u = __shfl_up_sync(0xffffffffu, wv, o);
            if (lane >= o) wv += u;
        }
        wsum[lane] = wv;
    }
    __syncthreads();
    int run = s - tot + (wid > 0 ? wsum[wid - 1] : 0);

    #pragma unroll
    for (int j = 0; j < 14; j++) {
        int4 v = c4[t * 14 + j];
        int idx = t * 56 + j * 4;
        if (idx + 3 < NN) {
            int4 o;
            o.x = run;             o.y = run + v.x;
            o.z = run + v.x + v.y; o.w = run + v.x + v.y + v.z;
            *(int4*)(g_rowptr + idx) = o;
            run += v.x + v.y + v.z + v.w;
        } else {
            if (idx     < NN) g_rowptr[idx]     = run; run += v.x;
            if (idx + 1 < NN) g_rowptr[idx + 1] = run; run += v.y;
            if (idx + 2 < NN) g_rowptr[idx + 2] = run; run += v.z;
            if (idx + 3 < NN) g_rowptr[idx + 3] = run; run += v.w;
        }
    }
    if (t == 1023) g_rowptr[NN] = EE;
}

__global__ void k_scatter(const int* __restrict__ src, const int* __restrict__ dst) {
    int i = blockIdx.x * blockDim.x + threadIdx.x;
    if (i >= EE) return;
    int d = dst[i];
    int pos = g_rowptr[d] + atomicAdd(&g_cnt[d], 1);
    g_csrc[pos] = src[i];
}

// ---------------------------------------------------------------------------
// tf32 tensor-core GEMM: z(fp16) = h @ W  (NNx128 @ 128x128).
// cp.async double-buffered staging (raw fp32 bits -> tf32 truncation),
// 256 threads (8 warps 4x2), warp tile 32x64, 2 blocks/SM.
// Layer 0: rows gathered from emb via nf.
// ---------------------------------------------------------------------------
__device__ __forceinline__ void mma8(float* c, const unsigned* a,
                                     unsigned b0, unsigned b1) {
    asm volatile(
        "mma.sync.aligned.m16n8k8.row.col.f32.tf32.tf32.f32 "
        "{%0,%1,%2,%3},{%4,%5,%6,%7},{%8,%9},{%0,%1,%2,%3};"
        : "+f"(c[0]), "+f"(c[1]), "+f"(c[2]), "+f"(c[3])
        : "r"(a[0]), "r"(a[1]), "r"(a[2]), "r"(a[3]), "r"(b0), "r"(b1));
}

__device__ __forceinline__ void cpasync16(void* smem, const void* gmem, int bytes) {
    unsigned s = (unsigned)__cvta_generic_to_shared(smem);
    asm volatile("cp.async.cg.shared.global [%0], [%1], 16, %2;"
                 :: "r"(s), "l"(gmem), "r"(bytes));
}
#define CP_COMMIT() asm volatile("cp.async.commit_group;")

#define SA_STRIDE 36
#define SB_STRIDE 136
#define SA_BUF (128 * SA_STRIDE)
#define SB_BUF (32 * SB_STRIDE)
#define GEMM_SMEM ((2 * SA_BUF + 2 * SB_BUF + 128) * 4)

__global__ __launch_bounds__(256, 2) void k_gemm(const float* __restrict__ hsrc,
                                                 const int* __restrict__ nf,
                                                 const float* __restrict__ W,
                                                 __half* __restrict__ z) {
    extern __shared__ unsigned smemraw[];
    unsigned* sA = smemraw;
    unsigned* sB = smemraw + 2 * SA_BUF;
    int* srow = (int*)(smemraw + 2 * SA_BUF + 2 * SB_BUF);

    int t = threadIdx.x;
    int rowbase = blockIdx.x * 128;
    if (t < 128) {
        int r = rowbase + t;
        srow[t] = (r < NN) ? (nf ? nf[r] : r) : -1;
    }
    __syncthreads();

    int warp = t >> 5, lane = t & 31;
    int qr = lane >> 2, qc = lane & 3;
    int wm = (warp >> 1) * 32;
    int wn = (warp & 1) * 64;

    // per-thread staging coordinates (4 float4 slots each for A and B)
    int arow[4], akq[4], bkr[4], bc4[4], asid[4];
    #pragma unroll
    for (int j = 0; j < 4; j++) {
        int idx = t + j * 256;
        arow[j] = idx >> 3;  akq[j] = idx & 7;
        bkr[j]  = idx >> 5;  bc4[j] = idx & 31;
        asid[j] = srow[arow[j]];
    }

    float c[2][8][4];
    #pragma unroll
    for (int mt = 0; mt < 2; mt++)
        #pragma unroll
        for (int nt = 0; nt < 8; nt++)
            #pragma unroll
            for (int i = 0; i < 4; i++) c[mt][nt][i] = 0.f;

    // stage chunk 0 into buf 0
    #pragma unroll
    for (int j = 0; j < 4; j++) {
        const void* ga = (asid[j] >= 0)
            ? (const void*)(hsrc + (long)asid[j] * 128 + akq[j] * 4)
            : (const void*)hsrc;
        cpasync16(sA + arow[j] * SA_STRIDE + akq[j] * 4, ga, asid[j] >= 0 ? 16 : 0);
        cpasync16(sB + bkr[j] * SB_STRIDE + bc4[j] * 4,
                  W + (long)bkr[j] * 128 + bc4[j] * 4, 16);
    }
    CP_COMMIT();

    #pragma unroll
    for (int kb = 0; kb < 4; kb++) {
        if (kb < 3) {
            int buf = (kb + 1) & 1;
            int ko = (kb + 1) * 32;
            unsigned* A = sA + buf * SA_BUF;
            unsigned* B = sB + buf * SB_BUF;
            #pragma unroll
            for (int j = 0; j < 4; j++) {
                const void* ga = (asid[j] >= 0)
                    ? (const void*)(hsrc + (long)asid[j] * 128 + ko + akq[j] * 4)
                    : (const void*)hsrc;
                cpasync16(A + arow[j] * SA_STRIDE + akq[j] * 4, ga, asid[j] >= 0 ? 16 : 0);
                cpasync16(B + bkr[j] * SB_STRIDE + bc4[j] * 4,
                          W + (long)(ko + bkr[j]) * 128 + bc4[j] * 4, 16);
            }
            CP_COMMIT();
            asm volatile("cp.async.wait_group 1;");
        } else {
            asm volatile("cp.async.wait_group 0;");
        }
        __syncthreads();

        const unsigned* A = sA + (kb & 1) * SA_BUF;
        const unsigned* B = sB + (kb & 1) * SB_BUF;
        #pragma unroll
        for (int kk = 0; kk < 4; kk++) {
            unsigned a[2][4];
            #pragma unroll
            for (int mt = 0; mt < 2; mt++) {
                int r = wm + mt * 16 + qr;
                a[mt][0] = A[(r)     * SA_STRIDE + kk * 8 + qc];
                a[mt][1] = A[(r + 8) * SA_STRIDE + kk * 8 + qc];
                a[mt][2] = A[(r)     * SA_STRIDE + kk * 8 + qc + 4];
                a[mt][3] = A[(r + 8) * SA_STRIDE + kk * 8 + qc + 4];
            }
            #pragma unroll
            for (int nt = 0; nt < 8; nt++) {
                int col = wn + nt * 8 + qr;
                unsigned b0 = B[(kk * 8 + qc)     * SB_STRIDE + col];
                unsigned b1 = B[(kk * 8 + qc + 4) * SB_STRIDE + col];
                #pragma unroll
                for (int mt = 0; mt < 2; mt++) mma8(c[mt][nt], a[mt], b0, b1);
            }
        }
        __syncthreads();
    }

    // epilogue: fp16 z
    #pragma unroll
    for (int mt = 0; mt < 2; mt++) {
        int r0 = rowbase + wm + mt * 16 + qr;
        int r1 = r0 + 8;
        #pragma unroll
        for (int nt = 0; nt < 8; nt++) {
            int col = wn + nt * 8 + qc * 2;
            if (r0 < NN)
                *(__half2*)(z + (long)r0 * 128 + col) = __floats2half2_rn(c[mt][nt][0], c[mt][nt][1]);
            if (r1 < NN)
                *(__half2*)(z + (long)r1 * 128 + col) = __floats2half2_rn(c[mt][nt][2], c[mt][nt][3]);
        }
    }
}

// ---------------------------------------------------------------------------
// el[n,h] = sum_o z[n,h,o]*al[h,o];  er likewise (z fp16)
// ---------------------------------------------------------------------------
__global__ void k_scores(const __half* __restrict__ z,
                         const float* __restrict__ al,
                         const float* __restrict__ ar,
                         float* __restrict__ el,
                         float* __restrict__ er) {
    int i = blockIdx.x * blockDim.x + threadIdx.x;
    if (i >= NN * 8) return;
    int n = i >> 3, hd = i & 7;
    const __half2* zp = (const __half2*)(z + (long)n * 128 + hd * 16);
    const float*  alp = al + hd * 16;
    const float*  arp = ar + hd * 16;
    float sl = 0.f, sr = 0.f;
    #pragma unroll
    for (int j = 0; j < 8; j++) {
        float2 zz = __half22float2(zp[j]);
        sl += zz.x * alp[j * 2] + zz.y * alp[j * 2 + 1];
        sr += zz.x * arp[j * 2] + zz.y * arp[j * 2 + 1];
    }
    el[i] = sl;
    er[i] = sr;
}

// ---------------------------------------------------------------------------
// Per-dst edge softmax + aggregate + residual + bias (+ leaky_relu).
// One warp/node; z gathered as fp16 (256B/edge). Residual via optional nfmap
// indirection (layer 0 reads emb[nf[n]] directly).
// ---------------------------------------------------------------------------
__global__ __launch_bounds__(256) void k_aggregate(const uint2* __restrict__ zh,
                                                   const float* __restrict__ el,
                                                   const float* __restrict__ er,
                                                   const float* __restrict__ hin,
                                                   const int* __restrict__ nfmap,
                                                   const float* __restrict__ bias,
                                                   float* __restrict__ hout,
                                                   int activate) {
    int warp = (blockIdx.x * blockDim.x + threadIdx.x) >> 5;
    int lane = threadIdx.x & 31;
    if (warp >= NN) return;
    int hd = lane >> 2;
    float erh = er[warp * 8 + hd];
    int beg = g_rowptr[warp], end = g_rowptr[warp + 1];
    float s = 0.f;
    float4 acc = make_float4(0.f, 0.f, 0.f, 0.f);

    int e = beg;
    for (; e + 4 <= end; e += 4) {
        int s0 = g_csrc[e],     s1 = g_csrc[e + 1];
        int s2 = g_csrc[e + 2], s3 = g_csrc[e + 3];
        float x0 = el[s0 * 8 + hd], x1 = el[s1 * 8 + hd];
        float x2 = el[s2 * 8 + hd], x3 = el[s3 * 8 + hd];
        uint2 qa = zh[(long)s0 * 32 + lane], qb = zh[(long)s1 * 32 + lane];
        uint2 qc = zh[(long)s2 * 32 + lane], qd = zh[(long)s3 * 32 + lane];
        x0 += erh; x0 = x0 > 0.f ? x0 : 0.2f * x0; float a0 = __expf(x0);
        x1 += erh; x1 = x1 > 0.f ? x1 : 0.2f * x1; float a1 = __expf(x1);
        x2 += erh; x2 = x2 > 0.f ? x2 : 0.2f * x2; float a2 = __expf(x2);
        x3 += erh; x3 = x3 > 0.f ? x3 : 0.2f * x3; float a3 = __expf(x3);
        float2 p, q;
        p = __half22float2(*(__half2*)&qa.x); q = __half22float2(*(__half2*)&qa.y);
        s += a0; acc.x += a0 * p.x; acc.y += a0 * p.y; acc.z += a0 * q.x; acc.w += a0 * q.y;
        p = __half22float2(*(__half2*)&qb.x); q = __half22float2(*(__half2*)&qb.y);
        s += a1; acc.x += a1 * p.x; acc.y += a1 * p.y; acc.z += a1 * q.x; acc.w += a1 * q.y;
        p = __half22float2(*(__half2*)&qc.x); q = __half22float2(*(__half2*)&qc.y);
        s += a2; acc.x += a2 * p.x; acc.y += a2 * p.y; acc.z += a2 * q.x; acc.w += a2 * q.y;
        p = __half22float2(*(__half2*)&qd.x); q = __half22float2(*(__half2*)&qd.y);
        s += a3; acc.x += a3 * p.x; acc.y += a3 * p.y; acc.z += a3 * q.x; acc.w += a3 * q.y;
    }
    for (; e < end; e++) {
        int sr = g_csrc[e];
        float x = el[sr * 8 + hd] + erh;
        x = x > 0.f ? x : 0.2f * x;
        float a = __expf(x);
        uint2 qa = zh[(long)sr * 32 + lane];
        float2 p = __half22float2(*(__half2*)&qa.x);
        float2 q = __half22float2(*(__half2*)&qa.y);
        s += a;
        acc.x += a * p.x; acc.y += a * p.y; acc.z += a * q.x; acc.w += a * q.y;
    }
    float inv = (s > 0.f) ? (1.f / s) : 0.f;
    int hidx = nfmap ? nfmap[warp] : warp;
    float4 hv = ((const float4*)hin)[(long)hidx * 32 + lane];
    float4 bv = ((const float4*)bias)[lane];
    float4 o;
    o.x = acc.x * inv + hv.x + bv.x;
    o.y = acc.y * inv + hv.y + bv.y;
    o.z = acc.z * inv + hv.z + bv.z;
    o.w = acc.w * inv + hv.w + bv.w;
    if (activate) {
        o.x = o.x > 0.f ? o.x : 0.01f * o.x;
        o.y = o.y > 0.f ? o.y : 0.01f * o.y;
        o.z = o.z > 0.f ? o.z : 0.01f * o.z;
        o.w = o.w > 0.f ? o.w : 0.01f * o.w;
    }
    ((float4*)hout)[warp * 32 + lane] = o;
}

// ---------------------------------------------------------------------------
// out[i] = normalize(h[x[i]])  -- one warp per (b,t)
// ---------------------------------------------------------------------------
__global__ void k_output(const float* __restrict__ h,
                         const int* __restrict__ x,
                         float* __restrict__ out) {
    int warp = (blockIdx.x * blockDim.x + threadIdx.x) >> 5;
    int lane = threadIdx.x & 31;
    if (warp >= BT) return;
    int idx = x[warp];
    float4 v = ((const float4*)h)[(long)idx * 32 + lane];
    float ss = v.x * v.x + v.y * v.y + v.z * v.z + v.w * v.w;
    #pragma unroll
    for (int o = 16; o; o >>= 1) ss += __shfl_xor_sync(0xffffffffu, ss, o);
    float inv = 1.f / fmaxf(sqrtf(ss), 1e-5f);
    ((float4*)out)[warp * 32 + lane] =
        make_float4(v.x * inv, v.y * inv, v.z * inv, v.w * inv);
}

// ---------------------------------------------------------------------------
// host launch
// ---------------------------------------------------------------------------
extern "C" void kernel_launch(void* const* d_in, const int* in_sizes, int n_in,
                              void* d_out, int out_size) {
    const float* emb = (const float*)d_in[0];
    const float* W0  = (const float*)d_in[1];
    const float* al0 = (const float*)d_in[2];
    const float* ar0 = (const float*)d_in[3];
    const float* b0  = (const float*)d_in[4];
    const float* W1  = (const float*)d_in[5];
    const float* al1 = (const float*)d_in[6];
    const float* ar1 = (const float*)d_in[7];
    const float* b1  = (const float*)d_in[8];
    const int*   nf  = (const int*)d_in[9];
    const int*   src = (const int*)d_in[10];
    const int*   dst = (const int*)d_in[11];
    const int*   x   = (const int*)d_in[12];
    float* out = (float*)d_out;

    float *h1, *hf, *el, *er;
    __half* z;
    int *cnt;
    cudaGetSymbolAddress((void**)&h1, g_h1);
    cudaGetSymbolAddress((void**)&hf, g_hf);
    cudaGetSymbolAddress((void**)&z,  g_z);
    cudaGetSymbolAddress((void**)&el, g_el);
    cudaGetSymbolAddress((void**)&er, g_er);
    cudaGetSymbolAddress((void**)&cnt, g_cnt);

    cudaFuncSetAttribute(k_gemm, cudaFuncAttributeMaxDynamicSharedMemorySize, GEMM_SMEM);

    const int T = 256;
    int gbCount  = (EE / 4 + T - 1) / T;
    int gbE      = (EE + T - 1) / T;
    int gbGemm   = (NN + 127) / 128;
    int gbScores = (NN * 8 + T - 1) / T;
    int gbAgg    = (NN * 32 + T - 1) / T;
    int gbOut    = (BT * 32 + T - 1) / T;

    // CSR build (same graph for both layers)
    cudaMemsetAsync(cnt, 0, NPAD * sizeof(int));
    k_count<<<gbCount, T>>>((const int4*)dst);
    k_scan<<<1, 1024>>>();
    cudaMemsetAsync(cnt, 0, NPAD * sizeof(int));
    k_scatter<<<gbE, T>>>(src, dst);

    // layer 0 (gather fused via nf; residual read as emb[nf[n]]; activation on)
    k_gemm<<<gbGemm, T, GEMM_SMEM>>>(emb, nf, W0, z);
    k_scores<<<gbScores, T>>>(z, al0, ar0, el, er);
    k_aggregate<<<gbAgg, T>>>((const uint2*)z, el, er, emb, nf, b0, h1, 1);

    // layer 1 (no activation)
    k_gemm<<<gbGemm, T, GEMM_SMEM>>>(h1, nullptr, W1, z);
    k_scores<<<gbScores, T>>>(z, al1, ar1, el, er);
    k_aggregate<<<gbAgg, T>>>((const uint2*)z, el, er, h1, nullptr, b1, hf, 0);

    // normalize + final gather
    k_output<<<gbOut, T>>>(hf, x, out);
}

// round 6
// speedup vs baseline: 1.6520x; 1.0881x over previous
#include <cuda_runtime.h>
#include <cuda_fp16.h>

// ---- problem constants (hardcoded in reference module) ----
#define NN 57254
#define EE 916064
#define NPAD 57344           // 1024*56, padded counter array
#define BT 32768             // B*T

// ---- device scratch (static: no allocation allowed) ----
__device__ float  g_h1[NN * 128];
__device__ float  g_hf[NN * 128];
__device__ __half g_z [NN * 128];
__device__ float  g_el[NN * 8];
__device__ float  g_er[NN * 8];
__device__ int    g_rowptr[NN + 1];
__device__ int    g_cnt[NPAD];
__device__ int    g_csrc[EE];

// ---------------------------------------------------------------------------
// CSR build: count (int4), single-block 2-pass scan, scatter
// ---------------------------------------------------------------------------
__global__ void k_count(const int4* __restrict__ dst4) {
    int i = blockIdx.x * blockDim.x + threadIdx.x;
    if (i < EE / 4) {
        int4 d = dst4[i];
        atomicAdd(&g_cnt[d.x], 1);
        atomicAdd(&g_cnt[d.y], 1);
        atomicAdd(&g_cnt[d.z], 1);
        atomicAdd(&g_cnt[d.w], 1);
    }
}

__global__ __launch_bounds__(1024) void k_scan() {
    __shared__ int wsum[32];
    int t = threadIdx.x;
    int lane = t & 31, wid = t >> 5;
    const int4* c4 = (const int4*)g_cnt;

    int tot = 0;
    #pragma unroll
    for (int j = 0; j < 14; j++) {
        int4 v = c4[t * 14 + j];
        tot += v.x + v.y + v.z + v.w;
    }
    int s = tot;
    #pragma unroll
    for (int o = 1; o < 32; o <<= 1) {
        int u = __shfl_up_sync(0xffffffffu, s, o);
        if (lane >= o) s += u;
    }
    if (lane == 31) wsum[wid] = s;
    __syncthreads();
    if (wid == 0) {
        int wv = wsum[lane];
        #pragma unroll
        for (int o = 1; o < 32; o <<= 1) {
            int u = __shfl_up_sync(0xffffffffu, wv, o);
            if (lane >= o) wv += u;
        }
        wsum[lane] = wv;
    }
    __syncthreads();
    int run = s - tot + (wid > 0 ? wsum[wid - 1] : 0);

    #pragma unroll
    for (int j = 0; j < 14; j++) {
        int4 v = c4[t * 14 + j];
        int idx = t * 56 + j * 4;
        if (idx + 3 < NN) {
            int4 o;
            o.x = run;             o.y = run + v.x;
            o.z = run + v.x + v.y; o.w = run + v.x + v.y + v.z;
            *(int4*)(g_rowptr + idx) = o;
            run += v.x + v.y + v.z + v.w;
        } else {
            if (idx     < NN) g_rowptr[idx]     = run; run += v.x;
            if (idx + 1 < NN) g_rowptr[idx + 1] = run; run += v.y;
            if (idx + 2 < NN) g_rowptr[idx + 2] = run; run += v.z;
            if (idx + 3 < NN) g_rowptr[idx + 3] = run; run += v.w;
        }
    }
    if (t == 1023) g_rowptr[NN] = EE;
}

__global__ void k_scatter(const int* __restrict__ src, const int* __restrict__ dst) {
    int i = blockIdx.x * blockDim.x + threadIdx.x;
    if (i >= EE) return;
    int d = dst[i];
    int pos = g_rowptr[d] + atomicAdd(&g_cnt[d], 1);
    g_csrc[pos] = src[i];
}

// ---------------------------------------------------------------------------
// tf32 tensor-core GEMM with fused scores:
//   z(fp16) = h @ W;  el = z . al (per head);  er = z . ar
// 64x128 block tile, 256 threads (8 warps 2x4), warp tile 32x32,
// cp.async double buffering, 3 blocks/SM.
// Layer 0: rows gathered from emb via nf.
// ---------------------------------------------------------------------------
__device__ __forceinline__ void mma8(float* c, const unsigned* a,
                                     unsigned b0, unsigned b1) {
    asm volatile(
        "mma.sync.aligned.m16n8k8.row.col.f32.tf32.tf32.f32 "
        "{%0,%1,%2,%3},{%4,%5,%6,%7},{%8,%9},{%0,%1,%2,%3};"
        : "+f"(c[0]), "+f"(c[1]), "+f"(c[2]), "+f"(c[3])
        : "r"(a[0]), "r"(a[1]), "r"(a[2]), "r"(a[3]), "r"(b0), "r"(b1));
}

__device__ __forceinline__ void cpasync16(void* smem, const void* gmem, int bytes) {
    unsigned s = (unsigned)__cvta_generic_to_shared(smem);
    asm volatile("cp.async.cg.shared.global [%0], [%1], 16, %2;"
                 :: "r"(s), "l"(gmem), "r"(bytes));
}
#define CP_COMMIT() asm volatile("cp.async.commit_group;")

#define SA_STRIDE 36
#define SB_STRIDE 136
#define SA_BUF (64 * SA_STRIDE)    // 2304 words
#define SB_BUF (32 * SB_STRIDE)    // 4352 words
#define GEMM_SMEM ((2 * SA_BUF + 2 * SB_BUF + 64) * 4)

__global__ __launch_bounds__(256, 3) void k_gemm(const float* __restrict__ hsrc,
                                                 const int* __restrict__ nf,
                                                 const float* __restrict__ W,
                                                 const float* __restrict__ al,
                                                 const float* __restrict__ ar,
                                                 __half* __restrict__ z,
                                                 float* __restrict__ el,
                                                 float* __restrict__ er) {
    extern __shared__ unsigned smemraw[];
    unsigned* sA = smemraw;
    unsigned* sB = smemraw + 2 * SA_BUF;
    int* srow = (int*)(smemraw + 2 * SA_BUF + 2 * SB_BUF);

    int t = threadIdx.x;
    int rowbase = blockIdx.x * 64;
    if (t < 64) {
        int r = rowbase + t;
        srow[t] = (r < NN) ? (nf ? nf[r] : r) : -1;
    }
    __syncthreads();

    int warp = t >> 5, lane = t & 31;
    int qr = lane >> 2, qc = lane & 3;
    int wm = (warp >> 2) * 32;      // 2 row groups
    int wn = (warp & 3) * 32;       // 4 col groups

    // staging coords: A 2 slots, B 4 slots per thread
    int arow[2], akq[2], asid[2];
    int bkr[4], bc4[4];
    #pragma unroll
    for (int j = 0; j < 2; j++) {
        int idx = t + j * 256;          // 0..511
        arow[j] = idx >> 3;  akq[j] = idx & 7;
        asid[j] = srow[arow[j]];
    }
    #pragma unroll
    for (int j = 0; j < 4; j++) {
        int idx = t + j * 256;          // 0..1023
        bkr[j] = idx >> 5;  bc4[j] = idx & 31;
    }

    float c[2][4][4];
    #pragma unroll
    for (int mt = 0; mt < 2; mt++)
        #pragma unroll
        for (int nt = 0; nt < 4; nt++)
            #pragma unroll
            for (int i = 0; i < 4; i++) c[mt][nt][i] = 0.f;

    // stage chunk 0 into buf 0
    #pragma unroll
    for (int j = 0; j < 2; j++) {
        const void* ga = (asid[j] >= 0)
            ? (const void*)(hsrc + (long)asid[j] * 128 + akq[j] * 4)
            : (const void*)hsrc;
        cpasync16(sA + arow[j] * SA_STRIDE + akq[j] * 4, ga, asid[j] >= 0 ? 16 : 0);
    }
    #pragma unroll
    for (int j = 0; j < 4; j++)
        cpasync16(sB + bkr[j] * SB_STRIDE + bc4[j] * 4,
                  W + (long)bkr[j] * 128 + bc4[j] * 4, 16);
    CP_COMMIT();

    #pragma unroll
    for (int kb = 0; kb < 4; kb++) {
        if (kb < 3) {
            int buf = (kb + 1) & 1;
            int ko = (kb + 1) * 32;
            unsigned* A = sA + buf * SA_BUF;
            unsigned* B = sB + buf * SB_BUF;
            #pragma unroll
            for (int j = 0; j < 2; j++) {
                const void* ga = (asid[j] >= 0)
                    ? (const void*)(hsrc + (long)asid[j] * 128 + ko + akq[j] * 4)
                    : (const void*)hsrc;
                cpasync16(A + arow[j] * SA_STRIDE + akq[j] * 4, ga, asid[j] >= 0 ? 16 : 0);
            }
            #pragma unroll
            for (int j = 0; j < 4; j++)
                cpasync16(B + bkr[j] * SB_STRIDE + bc4[j] * 4,
                          W + (long)(ko + bkr[j]) * 128 + bc4[j] * 4, 16);
            CP_COMMIT();
            asm volatile("cp.async.wait_group 1;");
        } else {
            asm volatile("cp.async.wait_group 0;");
        }
        __syncthreads();

        const unsigned* A = sA + (kb & 1) * SA_BUF;
        const unsigned* B = sB + (kb & 1) * SB_BUF;
        #pragma unroll
        for (int kk = 0; kk < 4; kk++) {
            unsigned a[2][4];
            #pragma unroll
            for (int mt = 0; mt < 2; mt++) {
                int r = wm + mt * 16 + qr;
                a[mt][0] = A[(r)     * SA_STRIDE + kk * 8 + qc];
                a[mt][1] = A[(r + 8) * SA_STRIDE + kk * 8 + qc];
                a[mt][2] = A[(r)     * SA_STRIDE + kk * 8 + qc + 4];
                a[mt][3] = A[(r + 8) * SA_STRIDE + kk * 8 + qc + 4];
            }
            #pragma unroll
            for (int nt = 0; nt < 4; nt++) {
                int col = wn + nt * 8 + qr;
                unsigned b0 = B[(kk * 8 + qc)     * SB_STRIDE + col];
                unsigned b1 = B[(kk * 8 + qc + 4) * SB_STRIDE + col];
                #pragma unroll
                for (int mt = 0; mt < 2; mt++) mma8(c[mt][nt], a[mt], b0, b1);
            }
        }
        __syncthreads();
    }

    // ---- epilogue 1: store z as fp16 ----
    #pragma unroll
    for (int mt = 0; mt < 2; mt++) {
        int r0 = rowbase + wm + mt * 16 + qr;
        int r1 = r0 + 8;
        #pragma unroll
        for (int nt = 0; nt < 4; nt++) {
            int col = wn + nt * 8 + qc * 2;
            if (r0 < NN)
                *(__half2*)(z + (long)r0 * 128 + col) = __floats2half2_rn(c[mt][nt][0], c[mt][nt][1]);
            if (r1 < NN)
                *(__half2*)(z + (long)r1 * 128 + col) = __floats2half2_rn(c[mt][nt][2], c[mt][nt][3]);
        }
    }

    // ---- epilogue 2: fused el/er scores ----
    // Head h occupies cols 16h..16h+15; a warp's 32-col window = 2 heads.
    // Each (row, head) sum lives in one quad -> 2x shfl_xor, leader stores.
    float alv[8], arv[8];
    #pragma unroll
    for (int nt = 0; nt < 4; nt++) {
        #pragma unroll
        for (int u = 0; u < 2; u++) {
            int col = wn + nt * 8 + qc * 2 + u;
            alv[nt * 2 + u] = __ldg(al + col);
            arv[nt * 2 + u] = __ldg(ar + col);
        }
    }
    #pragma unroll
    for (int mt = 0; mt < 2; mt++) {
        #pragma unroll
        for (int rh = 0; rh < 2; rh++) {
            #pragma unroll
            for (int hl = 0; hl < 2; hl++) {
                float pl = 0.f, pr = 0.f;
                #pragma unroll
                for (int k = 0; k < 2; k++) {
                    int nt = hl * 2 + k;
                    pl += c[mt][nt][rh * 2]     * alv[nt * 2]
                        + c[mt][nt][rh * 2 + 1] * alv[nt * 2 + 1];
                    pr += c[mt][nt][rh * 2]     * arv[nt * 2]
                        + c[mt][nt][rh * 2 + 1] * arv[nt * 2 + 1];
                }
                pl += __shfl_xor_sync(0xffffffffu, pl, 1);
                pl += __shfl_xor_sync(0xffffffffu, pl, 2);
                pr += __shfl_xor_sync(0xffffffffu, pr, 1);
                pr += __shfl_xor_sync(0xffffffffu, pr, 2);
                if ((lane & 3) == 0) {
                    int row = rowbase + wm + mt * 16 + qr + rh * 8;
                    if (row < NN) {
                        int hidx = (wn >> 4) + hl;
                        el[row * 8 + hidx] = pl;
                        er[row * 8 + hidx] = pr;
                    }
                }
            }
        }
    }
}

// ---------------------------------------------------------------------------
// Per-dst edge softmax + aggregate + residual + bias (+ leaky_relu / L2 norm).
// One warp/node; z gathered as fp16 (256B/edge). Residual via optional nfmap.
// ---------------------------------------------------------------------------
__global__ __launch_bounds__(256) void k_aggregate(const uint2* __restrict__ zh,
                                                   const float* __restrict__ el,
                                                   const float* __restrict__ er,
                                                   const float* __restrict__ hin,
                                                   const int* __restrict__ nfmap,
                                                   const float* __restrict__ bias,
                                                   float* __restrict__ hout,
                                                   int activate, int normalize) {
    int warp = (blockIdx.x * blockDim.x + threadIdx.x) >> 5;
    int lane = threadIdx.x & 31;
    if (warp >= NN) return;
    int hd = lane >> 2;
    float erh = er[warp * 8 + hd];
    int beg = g_rowptr[warp], end = g_rowptr[warp + 1];
    float s = 0.f;
    float4 acc = make_float4(0.f, 0.f, 0.f, 0.f);

    int e = beg;
    for (; e + 4 <= end; e += 4) {
        int s0 = g_csrc[e],     s1 = g_csrc[e + 1];
        int s2 = g_csrc[e + 2], s3 = g_csrc[e + 3];
        float x0 = el[s0 * 8 + hd], x1 = el[s1 * 8 + hd];
        float x2 = el[s2 * 8 + hd], x3 = el[s3 * 8 + hd];
        uint2 qa = zh[(long)s0 * 32 + lane], qb = zh[(long)s1 * 32 + lane];
        uint2 qc = zh[(long)s2 * 32 + lane], qd = zh[(long)s3 * 32 + lane];
        x0 += erh; x0 = x0 > 0.f ? x0 : 0.2f * x0; float a0 = __expf(x0);
        x1 += erh; x1 = x1 > 0.f ? x1 : 0.2f * x1; float a1 = __expf(x1);
        x2 += erh; x2 = x2 > 0.f ? x2 : 0.2f * x2; float a2 = __expf(x2);
        x3 += erh; x3 = x3 > 0.f ? x3 : 0.2f * x3; float a3 = __expf(x3);
        float2 p, q;
        p = __half22float2(*(__half2*)&qa.x); q = __half22float2(*(__half2*)&qa.y);
        s += a0; acc.x += a0 * p.x; acc.y += a0 * p.y; acc.z += a0 * q.x; acc.w += a0 * q.y;
        p = __half22float2(*(__half2*)&qb.x); q = __half22float2(*(__half2*)&qb.y);
        s += a1; acc.x += a1 * p.x; acc.y += a1 * p.y; acc.z += a1 * q.x; acc.w += a1 * q.y;
        p = __half22float2(*(__half2*)&qc.x); q = __half22float2(*(__half2*)&qc.y);
        s += a2; acc.x += a2 * p.x; acc.y += a2 * p.y; acc.z += a2 * q.x; acc.w += a2 * q.y;
        p = __half22float2(*(__half2*)&qd.x); q = __half22float2(*(__half2*)&qd.y);
        s += a3; acc.x += a3 * p.x; acc.y += a3 * p.y; acc.z += a3 * q.x; acc.w += a3 * q.y;
    }
    for (; e < end; e++) {
        int sr = g_csrc[e];
        float x = el[sr * 8 + hd] + erh;
        x = x > 0.f ? x : 0.2f * x;
        float a = __expf(x);
        uint2 qa = zh[(long)sr * 32 + lane];
        float2 p = __half22float2(*(__half2*)&qa.x);
        float2 q = __half22float2(*(__half2*)&qa.y);
        s += a;
        acc.x += a * p.x; acc.y += a * p.y; acc.z += a * q.x; acc.w += a * q.y;
    }
    float inv = (s > 0.f) ? (1.f / s) : 0.f;
    int hidx = nfmap ? nfmap[warp] : warp;
    float4 hv = ((const float4*)hin)[(long)hidx * 32 + lane];
    float4 bv = ((const float4*)bias)[lane];
    float4 o;
    o.x = acc.x * inv + hv.x + bv.x;
    o.y = acc.y * inv + hv.y + bv.y;
    o.z = acc.z * inv + hv.z + bv.z;
    o.w = acc.w * inv + hv.w + bv.w;
    if (activate) {
        o.x = o.x > 0.f ? o.x : 0.01f * o.x;
        o.y = o.y > 0.f ? o.y : 0.01f * o.y;
        o.z = o.z > 0.f ? o.z : 0.01f * o.z;
        o.w = o.w > 0.f ? o.w : 0.01f * o.w;
    }
    if (normalize) {
        float ss = o.x * o.x + o.y * o.y + o.z * o.z + o.w * o.w;
        #pragma unroll
        for (int off = 16; off; off >>= 1)
            ss += __shfl_xor_sync(0xffffffffu, ss, off);
        float inv2 = 1.f / fmaxf(sqrtf(ss), 1e-5f);
        o.x *= inv2; o.y *= inv2; o.z *= inv2; o.w *= inv2;
    }
    ((float4*)hout)[warp * 32 + lane] = o;
}

// ---------------------------------------------------------------------------
// out[i] = h[x[i]]  (pure gather; normalization already fused)
// ---------------------------------------------------------------------------
__global__ void k_output(const float4* __restrict__ h,
                         const int* __restrict__ x,
                         float4* __restrict__ out) {
    int i = blockIdx.x * blockDim.x + threadIdx.x;
    if (i >= BT * 32) return;
    int t = i >> 5, l = i & 31;
    out[i] = h[(long)x[t] * 32 + l];
}

// ---------------------------------------------------------------------------
// host launch
// ---------------------------------------------------------------------------
extern "C" void kernel_launch(void* const* d_in, const int* in_sizes, int n_in,
                              void* d_out, int out_size) {
    const float* emb = (const float*)d_in[0];
    const float* W0  = (const float*)d_in[1];
    const float* al0 = (const float*)d_in[2];
    const float* ar0 = (const float*)d_in[3];
    const float* b0  = (const float*)d_in[4];
    const float* W1  = (const float*)d_in[5];
    const float* al1 = (const float*)d_in[6];
    const float* ar1 = (const float*)d_in[7];
    const float* b1  = (const float*)d_in[8];
    const int*   nf  = (const int*)d_in[9];
    const int*   src = (const int*)d_in[10];
    const int*   dst = (const int*)d_in[11];
    const int*   x   = (const int*)d_in[12];
    float* out = (float*)d_out;

    float *h1, *hf, *el, *er;
    __half* z;
    int *cnt;
    cudaGetSymbolAddress((void**)&h1, g_h1);
    cudaGetSymbolAddress((void**)&hf, g_hf);
    cudaGetSymbolAddress((void**)&z,  g_z);
    cudaGetSymbolAddress((void**)&el, g_el);
    cudaGetSymbolAddress((void**)&er, g_er);
    cudaGetSymbolAddress((void**)&cnt, g_cnt);

    cudaFuncSetAttribute(k_gemm, cudaFuncAttributeMaxDynamicSharedMemorySize, GEMM_SMEM);

    const int T = 256;
    int gbCount = (EE / 4 + T - 1) / T;
    int gbE     = (EE + T - 1) / T;
    int gbGemm  = (NN + 63) / 64;
    int gbAgg   = (NN * 32 + T - 1) / T;
    int gbOut   = (BT * 32 + T - 1) / T;

    // CSR build (same graph for both layers)
    cudaMemsetAsync(cnt, 0, NPAD * sizeof(int));
    k_count<<<gbCount, T>>>((const int4*)dst);
    k_scan<<<1, 1024>>>();
    cudaMemsetAsync(cnt, 0, NPAD * sizeof(int));
    k_scatter<<<gbE, T>>>(src, dst);

    // layer 0 (gather fused via nf; scores fused; residual = emb[nf[n]])
    k_gemm<<<gbGemm, T, GEMM_SMEM>>>(emb, nf, W0, al0, ar0, z, el, er);
    k_aggregate<<<gbAgg, T>>>((const uint2*)z, el, er, emb, nf, b0, h1, 1, 0);

    // layer 1 (no activation; L2-normalize fused)
    k_gemm<<<gbGemm, T, GEMM_SMEM>>>(h1, nullptr, W1, al1, ar1, z, el, er);
    k_aggregate<<<gbAgg, T>>>((const uint2*)z, el, er, h1, nullptr, b1, hf, 0, 1);

    // final gather
    k_output<<<gbOut, T>>>((const float4*)hf, x, (float4*)out);
}

// round 7
// speedup vs baseline: 1.6554x; 1.0020x over previous
#include <cuda_runtime.h>
#include <cuda_fp16.h>

// ---- problem constants (hardcoded in reference module) ----
#define NN 57254
#define EE 916064
#define NPAD 57344           // 1024*56, padded counter array
#define BT 32768             // B*T

// ---- device scratch (static: no allocation allowed) ----
__device__ float  g_h1[NN * 128];     // layer-1 residual input (fp32)
__device__ float  g_hf[NN * 128];     // final normalized features
__device__ __half g_h0h[NN * 128];    // fp16 GEMM input, layer 0 (emb gathered)
__device__ __half g_h1h[NN * 128];    // fp16 GEMM input, layer 1
__device__ __half g_Wh0[128 * 128];
__device__ __half g_Wh1[128 * 128];
__device__ __half g_z [NN * 128];
__device__ float  g_el[NN * 8];
__device__ float  g_er[NN * 8];
__device__ int    g_rowptr[NN + 1];
__device__ int    g_cnt[NPAD];
__device__ int    g_csrc[EE];

// ---------------------------------------------------------------------------
// CSR build: count (int4), single-block 2-pass scan, scatter
// ---------------------------------------------------------------------------
__global__ void k_count(const int4* __restrict__ dst4) {
    int i = blockIdx.x * blockDim.x + threadIdx.x;
    if (i < EE / 4) {
        int4 d = dst4[i];
        atomicAdd(&g_cnt[d.x], 1);
        atomicAdd(&g_cnt[d.y], 1);
        atomicAdd(&g_cnt[d.z], 1);
        atomicAdd(&g_cnt[d.w], 1);
    }
}

__global__ __launch_bounds__(1024) void k_scan() {
    __shared__ int wsum[32];
    int t = threadIdx.x;
    int lane = t & 31, wid = t >> 5;
    const int4* c4 = (const int4*)g_cnt;

    int tot = 0;
    #pragma unroll
    for (int j = 0; j < 14; j++) {
        int4 v = c4[t * 14 + j];
        tot += v.x + v.y + v.z + v.w;
    }
    int s = tot;
    #pragma unroll
    for (int o = 1; o < 32; o <<= 1) {
        int u = __shfl_up_sync(0xffffffffu, s, o);
        if (lane >= o) s += u;
    }
    if (lane == 31) wsum[wid] = s;
    __syncthreads();
    if (wid == 0) {
        int wv = wsum[lane];
        #pragma unroll
        for (int o = 1; o < 32; o <<= 1) {
            int u = __shfl_up_sync(0xffffffffu, wv, o);
            if (lane >= o) wv += u;
        }
        wsum[lane] = wv;
    }
    __syncthreads();
    int run = s - tot + (wid > 0 ? wsum[wid - 1] : 0);

    #pragma unroll
    for (int j = 0; j < 14; j++) {
        int4 v = c4[t * 14 + j];
        int idx = t * 56 + j * 4;
        if (idx + 3 < NN) {
            int4 o;
            o.x = run;             o.y = run + v.x;
            o.z = run + v.x + v.y; o.w = run + v.x + v.y + v.z;
            *(int4*)(g_rowptr + idx) = o;
            run += v.x + v.y + v.z + v.w;
        } else {
            if (idx     < NN) g_rowptr[idx]     = run; run += v.x;
            if (idx + 1 < NN) g_rowptr[idx + 1] = run; run += v.y;
            if (idx + 2 < NN) g_rowptr[idx + 2] = run; run += v.z;
            if (idx + 3 < NN) g_rowptr[idx + 3] = run; run += v.w;
        }
    }
    if (t == 1023) g_rowptr[NN] = EE;
}

__global__ void k_scatter(const int* __restrict__ src, const int* __restrict__ dst) {
    int i = blockIdx.x * blockDim.x + threadIdx.x;
    if (i >= EE) return;
    int d = dst[i];
    int pos = g_rowptr[d] + atomicAdd(&g_cnt[d], 1);
    g_csrc[pos] = src[i];
}

// ---------------------------------------------------------------------------
// fp16 input prep: W0/W1 -> half; emb[nf[n]] -> half h0
// ---------------------------------------------------------------------------
__global__ void k_convW(const float* __restrict__ W0, const float* __restrict__ W1) {
    int i = blockIdx.x * blockDim.x + threadIdx.x;
    if (i < 128 * 128) {
        g_Wh0[i] = __float2half_rn(W0[i]);
        g_Wh1[i] = __float2half_rn(W1[i]);
    }
}

__global__ void k_gather_h(const float4* __restrict__ emb,
                           const int* __restrict__ nf) {
    int i = blockIdx.x * blockDim.x + threadIdx.x;   // NN*32 float4 slots
    if (i >= NN * 32) return;
    int n = i >> 5, l = i & 31;
    float4 v = emb[(long)nf[n] * 32 + l];
    __half2 lo = __floats2half2_rn(v.x, v.y);
    __half2 hi = __floats2half2_rn(v.z, v.w);
    uint2 u;
    u.x = *(unsigned*)&lo;
    u.y = *(unsigned*)&hi;
    *(uint2*)(g_h0h + (long)n * 128 + l * 4) = u;
}

// ---------------------------------------------------------------------------
// fp16 tensor-core GEMM with fused scores:
//   z(fp16) = h @ W;  el = z . al;  er = z . ar
// 64x128 block tile, 256 threads (8 warps 2x4), warp tile 32x32
// (m16n8k16). Full tiles staged once via cp.async; ldmatrix feeds mma.
// ---------------------------------------------------------------------------
__device__ __forceinline__ void mma16(float* c, const unsigned* a,
                                      unsigned b0, unsigned b1) {
    asm volatile(
        "mma.sync.aligned.m16n8k16.row.col.f32.f16.f16.f32 "
        "{%0,%1,%2,%3},{%4,%5,%6,%7},{%8,%9},{%0,%1,%2,%3};"
        : "+f"(c[0]), "+f"(c[1]), "+f"(c[2]), "+f"(c[3])
        : "r"(a[0]), "r"(a[1]), "r"(a[2]), "r"(a[3]), "r"(b0), "r"(b1));
}

__device__ __forceinline__ void ldmx4(unsigned* r, unsigned addr) {
    asm volatile("ldmatrix.sync.aligned.m8n8.x4.shared.b16 {%0,%1,%2,%3}, [%4];"
                 : "=r"(r[0]), "=r"(r[1]), "=r"(r[2]), "=r"(r[3]) : "r"(addr));
}

__device__ __forceinline__ void ldmx4t(unsigned* r, unsigned addr) {
    asm volatile("ldmatrix.sync.aligned.m8n8.x4.trans.shared.b16 {%0,%1,%2,%3}, [%4];"
                 : "=r"(r[0]), "=r"(r[1]), "=r"(r[2]), "=r"(r[3]) : "r"(addr));
}

__device__ __forceinline__ void cpasync16(void* smem, const void* gmem, int bytes) {
    unsigned s = (unsigned)__cvta_generic_to_shared(smem);
    asm volatile("cp.async.cg.shared.global [%0], [%1], 16, %2;"
                 :: "r"(s), "l"(gmem), "r"(bytes));
}
#define CP_COMMIT() asm volatile("cp.async.commit_group;")

#define HST 136                          // halves per smem row (272 B)
#define GEMM_SMEM ((64 * HST + 128 * HST) * 2)

__global__ __launch_bounds__(256, 3) void k_gemm(const __half* __restrict__ Ah,
                                                 const __half* __restrict__ Wh,
                                                 const float* __restrict__ al,
                                                 const float* __restrict__ ar,
                                                 __half* __restrict__ z,
                                                 float* __restrict__ el,
                                                 float* __restrict__ er) {
    extern __shared__ __half smh[];
    __half* sA = smh;               // 64 x HST
    __half* sB = smh + 64 * HST;    // 128 x HST (W, k-major)

    int t = threadIdx.x;
    int rowbase = blockIdx.x * 64;
    int warp = t >> 5, lane = t & 31;
    int qr = lane >> 2, qc = lane & 3;
    int wm = (warp >> 2) * 32;
    int wn = (warp & 3) * 32;

    // ---- stage full A (64x128) and B (128x128) tiles ----
    #pragma unroll
    for (int j = 0; j < 4; j++) {
        int idx = t + j * 256;          // 0..1023
        int row = idx >> 4, seg = idx & 15;
        int gr = rowbase + row;
        const void* ga = (gr < NN) ? (const void*)(Ah + (long)gr * 128 + seg * 8)
                                   : (const void*)Ah;
        cpasync16(sA + row * HST + seg * 8, ga, gr < NN ? 16 : 0);
    }
    #pragma unroll
    for (int j = 0; j < 8; j++) {
        int idx = t + j * 256;          // 0..2047
        int row = idx >> 4, seg = idx & 15;
        cpasync16(sB + row * HST + seg * 8, Wh + (long)row * 128 + seg * 8, 16);
    }
    CP_COMMIT();

    float c[2][4][4];
    #pragma unroll
    for (int mt = 0; mt < 2; mt++)
        #pragma unroll
        for (int nt = 0; nt < 4; nt++)
            #pragma unroll
            for (int i = 0; i < 4; i++) c[mt][nt][i] = 0.f;

    // per-lane ldmatrix base addresses (bytes, shared space)
    unsigned sAsh = (unsigned)__cvta_generic_to_shared(sA);
    unsigned sBsh = (unsigned)__cvta_generic_to_shared(sB);
    int l8  = lane & 7;
    int m01 = (lane >> 3) & 1;     // matrix pair selector (row +8)
    int hi  = lane >> 4;           // k-hi / n-hi selector
    unsigned aAddr0 = sAsh + ((wm + m01 * 8 + l8) * HST + hi * 8) * 2;
    unsigned aAddr1 = aAddr0 + 16 * HST * 2;
    unsigned bAddr0 = sBsh + ((m01 * 8 + l8) * HST + wn + hi * 8) * 2;
    unsigned bAddr1 = bAddr0 + 16 * 2;

    asm volatile("cp.async.wait_group 0;");
    __syncthreads();

    #pragma unroll
    for (int ks = 0; ks < 8; ks++) {
        unsigned a0[4], a1[4], b0[4], b1[4];
        ldmx4 (a0, aAddr0 + ks * 32);
        ldmx4 (a1, aAddr1 + ks * 32);
        ldmx4t(b0, bAddr0 + ks * 16 * HST * 2);
        ldmx4t(b1, bAddr1 + ks * 16 * HST * 2);
        // b0 = {b0@nt0, b1@nt0, b0@nt1, b1@nt1}; b1 = nt2, nt3
        mma16(c[0][0], a0, b0[0], b0[1]);
        mma16(c[1][0], a1, b0[0], b0[1]);
        mma16(c[0][1], a0, b0[2], b0[3]);
        mma16(c[1][1], a1, b0[2], b0[3]);
        mma16(c[0][2], a0, b1[0], b1[1]);
        mma16(c[1][2], a1, b1[0], b1[1]);
        mma16(c[0][3], a0, b1[2], b1[3]);
        mma16(c[1][3], a1, b1[2], b1[3]);
    }

    // ---- epilogue 1: store z as fp16 ----
    #pragma unroll
    for (int mt = 0; mt < 2; mt++) {
        int r0 = rowbase + wm + mt * 16 + qr;
        int r1 = r0 + 8;
        #pragma unroll
        for (int nt = 0; nt < 4; nt++) {
            int col = wn + nt * 8 + qc * 2;
            if (r0 < NN)
                *(__half2*)(z + (long)r0 * 128 + col) = __floats2half2_rn(c[mt][nt][0], c[mt][nt][1]);
            if (r1 < NN)
                *(__half2*)(z + (long)r1 * 128 + col) = __floats2half2_rn(c[mt][nt][2], c[mt][nt][3]);
        }
    }

    // ---- epilogue 2: fused el/er scores (head = 16 cols; warp = 2 heads) ----
    float alv[8], arv[8];
    #pragma unroll
    for (int nt = 0; nt < 4; nt++) {
        #pragma unroll
        for (int u = 0; u < 2; u++) {
            int col = wn + nt * 8 + qc * 2 + u;
            alv[nt * 2 + u] = __ldg(al + col);
            arv[nt * 2 + u] = __ldg(ar + col);
        }
    }
    #pragma unroll
    for (int mt = 0; mt < 2; mt++) {
        #pragma unroll
        for (int rh = 0; rh < 2; rh++) {
            #pragma unroll
            for (int hl = 0; hl < 2; hl++) {
                float pl = 0.f, pr = 0.f;
                #pragma unroll
                for (int k = 0; k < 2; k++) {
                    int nt = hl * 2 + k;
                    pl += c[mt][nt][rh * 2]     * alv[nt * 2]
                        + c[mt][nt][rh * 2 + 1] * alv[nt * 2 + 1];
                    pr += c[mt][nt][rh * 2]     * arv[nt * 2]
                        + c[mt][nt][rh * 2 + 1] * arv[nt * 2 + 1];
                }
                pl += __shfl_xor_sync(0xffffffffu, pl, 1);
                pl += __shfl_xor_sync(0xffffffffu, pl, 2);
                pr += __shfl_xor_sync(0xffffffffu, pr, 1);
                pr += __shfl_xor_sync(0xffffffffu, pr, 2);
                if ((lane & 3) == 0) {
                    int row = rowbase + wm + mt * 16 + qr + rh * 8;
                    if (row < NN) {
                        int hidx = (wn >> 4) + hl;
                        el[row * 8 + hidx] = pl;
                        er[row * 8 + hidx] = pr;
                    }
                }
            }
        }
    }
}

// ---------------------------------------------------------------------------
// Per-dst edge softmax + aggregate + residual + bias (+ leaky_relu / L2 norm).
// One warp/node; z gathered as fp16. Optional fp16 twin output for next GEMM.
// ---------------------------------------------------------------------------
__global__ __launch_bounds__(256) void k_aggregate(const uint2* __restrict__ zh,
                                                   const float* __restrict__ el,
                                                   const float* __restrict__ er,
                                                   const float* __restrict__ hin,
                                                   const int* __restrict__ nfmap,
                                                   const float* __restrict__ bias,
                                                   float* __restrict__ hout,
                                                   __half* __restrict__ houth,
                                                   int activate, int normalize) {
    int warp = (blockIdx.x * blockDim.x + threadIdx.x) >> 5;
    int lane = threadIdx.x & 31;
    if (warp >= NN) return;
    int hd = lane >> 2;
    float erh = er[warp * 8 + hd];
    int beg = g_rowptr[warp], end = g_rowptr[warp + 1];
    float s = 0.f;
    float4 acc = make_float4(0.f, 0.f, 0.f, 0.f);

    int e = beg;
    for (; e + 4 <= end; e += 4) {
        int s0 = g_csrc[e],     s1 = g_csrc[e + 1];
        int s2 = g_csrc[e + 2], s3 = g_csrc[e + 3];
        float x0 = el[s0 * 8 + hd], x1 = el[s1 * 8 + hd];
        float x2 = el[s2 * 8 + hd], x3 = el[s3 * 8 + hd];
        uint2 qa = zh[(long)s0 * 32 + lane], qb = zh[(long)s1 * 32 + lane];
        uint2 qc = zh[(long)s2 * 32 + lane], qd = zh[(long)s3 * 32 + lane];
        x0 += erh; x0 = x0 > 0.f ? x0 : 0.2f * x0; float a0 = __expf(x0);
        x1 += erh; x1 = x1 > 0.f ? x1 : 0.2f * x1; float a1 = __expf(x1);
        x2 += erh; x2 = x2 > 0.f ? x2 : 0.2f * x2; float a2 = __expf(x2);
        x3 += erh; x3 = x3 > 0.f ? x3 : 0.2f * x3; float a3 = __expf(x3);
        float2 p, q;
        p = __half22float2(*(__half2*)&qa.x); q = __half22float2(*(__half2*)&qa.y);
        s += a0; acc.x += a0 * p.x; acc.y += a0 * p.y; acc.z += a0 * q.x; acc.w += a0 * q.y;
        p = __half22float2(*(__half2*)&qb.x); q = __half22float2(*(__half2*)&qb.y);
        s += a1; acc.x += a1 * p.x; acc.y += a1 * p.y; acc.z += a1 * q.x; acc.w += a1 * q.y;
        p = __half22float2(*(__half2*)&qc.x); q = __half22float2(*(__half2*)&qc.y);
        s += a2; acc.x += a2 * p.x; acc.y += a2 * p.y; acc.z += a2 * q.x; acc.w += a2 * q.y;
        p = __half22float2(*(__half2*)&qd.x); q = __half22float2(*(__half2*)&qd.y);
        s += a3; acc.x += a3 * p.x; acc.y += a3 * p.y; acc.z += a3 * q.x; acc.w += a3 * q.y;
    }
    for (; e < end; e++) {
        int sr = g_csrc[e];
        float x = el[sr * 8 + hd] + erh;
        x = x > 0.f ? x : 0.2f * x;
        float a = __expf(x);
        uint2 qa = zh[(long)sr * 32 + lane];
        float2 p = __half22float2(*(__half2*)&qa.x);
        float2 q = __half22float2(*(__half2*)&qa.y);
        s += a;
        acc.x += a * p.x; acc.y += a * p.y; acc.z += a * q.x; acc.w += a * q.y;
    }
    float inv = (s > 0.f) ? (1.f / s) : 0.f;
    int hidx = nfmap ? nfmap[warp] : warp;
    float4 hv = ((const float4*)hin)[(long)hidx * 32 + lane];
    float4 bv = ((const float4*)bias)[lane];
    float4 o;
    o.x = acc.x * inv + hv.x + bv.x;
    o.y = acc.y * inv + hv.y + bv.y;
    o.z = acc.z * inv + hv.z + bv.z;
    o.w = acc.w * inv + hv.w + bv.w;
    if (activate) {
        o.x = o.x > 0.f ? o.x : 0.01f * o.x;
        o.y = o.y > 0.f ? o.y : 0.01f * o.y;
        o.z = o.z > 0.f ? o.z : 0.01f * o.z;
        o.w = o.w > 0.f ? o.w : 0.01f * o.w;
    }
    if (normalize) {
        float ss = o.x * o.x + o.y * o.y + o.z * o.z + o.w * o.w;
        #pragma unroll
        for (int off = 16; off; off >>= 1)
            ss += __shfl_xor_sync(0xffffffffu, ss, off);
        float inv2 = 1.f / fmaxf(sqrtf(ss), 1e-5f);
        o.x *= inv2; o.y *= inv2; o.z *= inv2; o.w *= inv2;
    }
    ((float4*)hout)[warp * 32 + lane] = o;
    if (houth) {
        __half2 lo = __floats2half2_rn(o.x, o.y);
        __half2 hi = __floats2half2_rn(o.z, o.w);
        uint2 u;
        u.x = *(unsigned*)&lo;
        u.y = *(unsigned*)&hi;
        *(uint2*)(houth + (long)warp * 128 + lane * 4) = u;
    }
}

// ---------------------------------------------------------------------------
// out[i] = h[x[i]]  (pure gather; normalization already fused)
// ---------------------------------------------------------------------------
__global__ void k_output(const float4* __restrict__ h,
                         const int* __restrict__ x,
                         float4* __restrict__ out) {
    int i = blockIdx.x * blockDim.x + threadIdx.x;
    if (i >= BT * 32) return;
    int t = i >> 5, l = i & 31;
    out[i] = h[(long)x[t] * 32 + l];
}

// ---------------------------------------------------------------------------
// host launch
// ---------------------------------------------------------------------------
extern "C" void kernel_launch(void* const* d_in, const int* in_sizes, int n_in,
                              void* d_out, int out_size) {
    const float* emb = (const float*)d_in[0];
    const float* W0  = (const float*)d_in[1];
    const float* al0 = (const float*)d_in[2];
    const float* ar0 = (const float*)d_in[3];
    const float* b0  = (const float*)d_in[4];
    const float* W1  = (const float*)d_in[5];
    const float* al1 = (const float*)d_in[6];
    const float* ar1 = (const float*)d_in[7];
    const float* b1  = (const float*)d_in[8];
    const int*   nf  = (const int*)d_in[9];
    const int*   src = (const int*)d_in[10];
    const int*   dst = (const int*)d_in[11];
    const int*   x   = (const int*)d_in[12];
    float* out = (float*)d_out;

    float *h1, *hf, *el, *er;
    __half *z, *h0h, *h1h, *Wh0, *Wh1;
    int *cnt;
    cudaGetSymbolAddress((void**)&h1,  g_h1);
    cudaGetSymbolAddress((void**)&hf,  g_hf);
    cudaGetSymbolAddress((void**)&z,   g_z);
    cudaGetSymbolAddress((void**)&h0h, g_h0h);
    cudaGetSymbolAddress((void**)&h1h, g_h1h);
    cudaGetSymbolAddress((void**)&Wh0, g_Wh0);
    cudaGetSymbolAddress((void**)&Wh1, g_Wh1);
    cudaGetSymbolAddress((void**)&el,  g_el);
    cudaGetSymbolAddress((void**)&er,  g_er);
    cudaGetSymbolAddress((void**)&cnt, g_cnt);

    cudaFuncSetAttribute(k_gemm, cudaFuncAttributeMaxDynamicSharedMemorySize, GEMM_SMEM);

    const int T = 256;
    int gbCount = (EE / 4 + T - 1) / T;
    int gbE     = (EE + T - 1) / T;
    int gbGemm  = (NN + 63) / 64;
    int gbConv  = (128 * 128 + T - 1) / T;
    int gbGat   = (NN * 32 + T - 1) / T;
    int gbAgg   = (NN * 32 + T - 1) / T;
    int gbOut   = (BT * 32 + T - 1) / T;

    // CSR build (same graph for both layers)
    cudaMemsetAsync(cnt, 0, NPAD * sizeof(int));
    k_count<<<gbCount, T>>>((const int4*)dst);
    k_scan<<<1, 1024>>>();
    cudaMemsetAsync(cnt, 0, NPAD * sizeof(int));
    k_scatter<<<gbE, T>>>(src, dst);

    // fp16 input prep
    k_convW<<<gbConv, T>>>(W0, W1);
    k_gather_h<<<gbGat, T>>>((const float4*)emb, nf);

    // layer 0 (scores fused; residual = emb[nf[n]]; writes fp16 twin h1h)
    k_gemm<<<gbGemm, T, GEMM_SMEM>>>(h0h, Wh0, al0, ar0, z, el, er);
    k_aggregate<<<gbAgg, T>>>((const uint2*)z, el, er, emb, nf, b0, h1, h1h, 1, 0);

    // layer 1 (no activation; L2-normalize fused)
    k_gemm<<<gbGemm, T, GEMM_SMEM>>>(h1h, Wh1, al1, ar1, z, el, er);
    k_aggregate<<<gbAgg, T>>>((const uint2*)z, el, er, h1, nullptr, b1, hf, nullptr, 0, 1);

    // final gather
    k_output<<<gbOut, T>>>((const float4*)hf, x, (float4*)out);
}